// round 6
// baseline (speedup 1.0000x reference)
#include <cuda_runtime.h>
#include <math.h>

#define TWO_PI_F  6.28318530717958647692f
#define TWO_PI2_F 19.739208802178716f   /* 2*pi^2 */

#define NMAX 8192
#define PMAX 64
#define KPAD 520
#define ACH 16             /* k per adjoint chunk (multiple of 4!) */
#define AZ 8               /* adjoint N-splits */
#define AE 4               /* elements per adjoint thread */
#define PROJ_PTS 128
#define PG 2               /* slices per forward block */

typedef unsigned long long u64p;

// ---------- packed f32x2 helpers ----------
__device__ __forceinline__ u64p pk2(float lo, float hi) {
    u64p r; asm("mov.b64 %0, {%1, %2};" : "=l"(r) : "f"(lo), "f"(hi)); return r;
}
__device__ __forceinline__ void upk2(u64p v, float& lo, float& hi) {
    asm("mov.b64 {%0, %1}, %2;" : "=f"(lo), "=f"(hi) : "l"(v));
}
__device__ __forceinline__ u64p fma2(u64p a, u64p b, u64p c) {
    u64p d; asm("fma.rn.f32x2 %0, %1, %2, %3;" : "=l"(d) : "l"(a), "l"(b), "l"(c)); return d;
}

// ---------- device scratch ----------
__device__ float  g_A[PMAX * NMAX];    // sf * <x_n, xi_p>, [p][n]
__device__ float  g_B[PMAX * NMAX];    // sf * <y_m, xi_p>, [p][m]
__device__ float2 g_CS[PMAX * KPAD];   // (C*kft2, S*kft2), slot j = k-1
__device__ float  g_kft2[KPAD];        // 2*kft(h)/P, thresholded
__device__ float  g_blockmax[256];
__device__ int    g_hmax;
__device__ int    g_kmin;
__device__ float  g_sf;

// ---------- norm + init fused ----------
__global__ void norm_init_kernel(const float* __restrict__ x, const float* __restrict__ y,
                                 float* __restrict__ out, int N, int M, int d) {
    __shared__ float wmax[8];
    int i = blockIdx.x * blockDim.x + threadIdx.x;
    int stride = gridDim.x * blockDim.x;
    float2 z2 = make_float2(0.f, 0.f);
    for (int j = i; j < PMAX * KPAD; j += stride) g_CS[j] = z2;
    for (int j = i; j < M; j += stride) out[j] = 0.f;
    float v = 0.f;
    int T = N + M;
    if (i < T) {
        const float* row = (i < N) ? (x + (size_t)i * d) : (y + (size_t)(i - N) * d);
        float s = 0.f;
        for (int j = 0; j < d; j += 4) {
            float4 q = *reinterpret_cast<const float4*>(row + j);
            s = fmaf(q.x, q.x, s); s = fmaf(q.y, q.y, s);
            s = fmaf(q.z, q.z, s); s = fmaf(q.w, q.w, s);
        }
        v = s;
    }
#pragma unroll
    for (int off = 16; off > 0; off >>= 1)
        v = fmaxf(v, __shfl_xor_sync(0xffffffffu, v, off));
    if ((threadIdx.x & 31) == 0) wmax[threadIdx.x >> 5] = v;
    __syncthreads();
    if (threadIdx.x == 0) {
        float m = wmax[0];
#pragma unroll
        for (int wq = 1; wq < 8; wq++) m = fmaxf(m, wmax[wq]);
        g_blockmax[blockIdx.x] = m;
    }
}

// ---------- Fourier coefficients, cutoff ----------
__global__ void kft_kernel(const float* __restrict__ scale, int P, float dd, int nb) {
    __shared__ float sred[512];
    int tid = threadIdx.x;
    if (tid == 0) { g_hmax = 0; g_kmin = 0x7fffffff; }
    float bm = (tid < nb) ? g_blockmax[tid] : 0.f;
    sred[tid] = bm;
    __syncthreads();
    for (int s = 256; s > 0; s >>= 1) {
        if (tid < s) sred[tid] = fmaxf(sred[tid], sred[tid + s]);
        __syncthreads();
    }
    float nm = sqrtf(sred[0]);
    float sf = 0.3f / nm;
    float sr = scale[0] * sf;
    float s2 = sr * sr;
    int h = tid + 1;
    float kft = 0.f;
    if (h <= 511) {
        float hp = (float)h;
        float logv = 0.5f * dd * logf(TWO_PI2_F * s2)
                   + (dd - 1.f) * logf(hp)
                   - TWO_PI2_F * s2 * hp * hp
                   - lgammaf(0.5f * dd);
        kft = expf(logv);
    }
    __syncthreads();
    sred[tid] = kft;
    __syncthreads();
    for (int s = 256; s > 0; s >>= 1) {
        if (tid < s) sred[tid] = fmaxf(sred[tid], sred[tid + s]);
        __syncthreads();
    }
    float maxv = sred[0];
    float thr = maxv * 1e-7f;
    bool keep = (h <= 511) && (maxv > 0.f) && (kft > thr);
    if (h <= 511) g_kft2[h] = keep ? kft * (2.f / (float)P) : 0.f;
    if (keep) { atomicMax(&g_hmax, h); atomicMin(&g_kmin, h); }
    if (tid == 0) { g_sf = sf; g_kft2[0] = 0.f; }
    if (tid < 8) g_kft2[512 + tid] = 0.f;
}

// ---------- proj4: smem-staged, full P in one pass, packed fma2 ----------
__global__ void __launch_bounds__(256) proj4_kernel(const float* __restrict__ xpts,
                                                    const float* __restrict__ ypts,
                                                    const float* __restrict__ xis,
                                                    int N, int M, int P) {
    __shared__ float xi_t[64 * 66];
    __shared__ float pts_s[PROJ_PTS * 65];
    int tid = threadIdx.x;
    int which = blockIdx.y;
    const float* pts = which ? ypts : xpts;
    int npts = which ? M : N;
    int base = blockIdx.x * PROJ_PTS;

    for (int idx = tid; idx < 64 * 64; idx += 256) {
        int p = idx >> 6, dc = idx & 63;
        xi_t[dc * 66 + p] = (p < P) ? xis[idx] : 0.f;
    }
    for (int idx = tid; idx < PROJ_PTS * 16; idx += 256) {
        int r = idx >> 4, j4 = idx & 15;
        int n = base + r;
        float4 v = make_float4(0.f, 0.f, 0.f, 0.f);
        if (n < npts) v = *reinterpret_cast<const float4*>(pts + (size_t)n * 64 + j4 * 4);
        float* dp = pts_s + r * 65 + j4 * 4;
        dp[0] = v.x; dp[1] = v.y; dp[2] = v.z; dp[3] = v.w;
    }
    __syncthreads();

    int slot = tid & 63;
    int g = tid >> 6;
    const float* r0 = pts_s + slot * 65;
    const float* r1 = pts_s + (slot + 64) * 65;

    u64p acc0[8], acc1[8];
#pragma unroll
    for (int q = 0; q < 8; q++) { acc0[q] = 0ull; acc1[q] = 0ull; }

#pragma unroll 4
    for (int j = 0; j < 64; j++) {
        float v0 = r0[j], v1 = r1[j];
        u64p vv0 = pk2(v0, v0);
        u64p vv1 = pk2(v1, v1);
        const float* xb = xi_t + j * 66 + g * 16;
#pragma unroll
        for (int q = 0; q < 8; q++) {
            u64p xq = *reinterpret_cast<const u64p*>(xb + 2 * q);
            acc0[q] = fma2(vv0, xq, acc0[q]);
            acc1[q] = fma2(vv1, xq, acc1[q]);
        }
    }

    float sf = g_sf;
    float* dst = which ? g_B : g_A;
    int n0 = base + slot, n1 = n0 + 64;
#pragma unroll
    for (int q = 0; q < 8; q++) {
        float a, b, c, dq;
        upk2(acc0[q], a, b);
        upk2(acc1[q], c, dq);
        int p0 = g * 16 + 2 * q;
        if (p0 < P) {
            if (n0 < npts) dst[(size_t)p0 * npts + n0] = a * sf;
            if (n1 < npts) dst[(size_t)p0 * npts + n1] = c * sf;
        }
        if (p0 + 1 < P) {
            if (n0 < npts) dst[(size_t)(p0 + 1) * npts + n0] = b * sf;
            if (n1 < npts) dst[(size_t)(p0 + 1) * npts + n1] = dq * sf;
        }
    }
}

// ---------- adjoint: chunk-carried Chebyshev, elements resident in registers ----------
// Thread owns AE=4 elements; rotation state persists across ALL k-chunks so
// loads + 4 sincos happen ONCE per element. Rotation sign (-1)^j, accumulate
// uniform +w; slot sign sigma_j=[+,+,-,-] applied at dump (with kft2 fold).
__global__ void __launch_bounds__(256) adjoint_kernel(const float* __restrict__ w, int N) {
    int p = blockIdx.x;
    int z = blockIdx.y;
    int hmax = g_hmax;
    if (hmax < 1) return;
    int klo = g_kmin; if (klo < 1) klo = 1;
    int nchunk = (hmax - klo + ACH) / ACH;

    __shared__ float sP[32 * 33];
    int tid = threadIdx.x;
    const float* arow = g_A + (size_t)p * N;
    int seg = (N + AZ - 1) / AZ;
    int st = z * seg;
    int en = st + seg; if (en > N) en = N;

    float fklo = (float)klo;
    u64p vc[AE], vp[AE], t2p[AE], nt2p[AE], wp[AE];
#pragma unroll
    for (int e = 0; e < AE; e++) {
        int n = st + tid + e * 256;
        bool ok = (n < en);
        float a  = ok ? arow[n] : 0.f;
        float ww = ok ? w[n]    : 0.f;
        float us, uc;
        __sincosf(TWO_PI_F * a, &us, &uc);
        float t = fklo * a;
        float er = fmaf(fklo, a, -t);
        float f = (t - rintf(t)) + er;
        float zs, zc;
        __sincosf(TWO_PI_F * f, &zs, &zc);
        float zmc = fmaf(zc, uc,  zs * us);   // z_{klo-1} = z_klo * conj(u)
        float zms = fmaf(zs, uc, -zc * us);
        vc[e] = pk2(zc, zs);
        vp[e] = pk2(-zmc, -zms);
        t2p[e]  = pk2( 2.f * uc,  2.f * uc);
        nt2p[e] = pk2(-2.f * uc, -2.f * uc);
        wp[e] = pk2(ww, ww);
    }

    for (int c = 0; c < nchunk; c++) {
        int k0 = klo + c * ACH;
        u64p accv[ACH];
#pragma unroll
        for (int j = 0; j < ACH; j++) accv[j] = 0ull;

#pragma unroll
        for (int j = 0; j < ACH; j++) {
#pragma unroll
            for (int e = 0; e < AE; e++) {
                accv[j] = fma2(wp[e], vc[e], accv[j]);
                u64p vn = fma2((j & 1) ? nt2p[e] : t2p[e], vc[e], vp[e]);
                vp[e] = vc[e]; vc[e] = vn;
            }
        }

        for (int i = tid; i < 32 * 33; i += 256) sP[i] = 0.f;
        __syncthreads();
        float* myrow = sP + (tid & 31) * 33;
#pragma unroll
        for (int j = 0; j < ACH; j++) {
            float cc, ss;
            upk2(accv[j], cc, ss);
            atomicAdd(myrow + 2 * j, cc);
            atomicAdd(myrow + 2 * j + 1, ss);
        }
        __syncthreads();
        if (tid < 2 * ACH) {
            int jj = tid;
            float sum = 0.f;
#pragma unroll
            for (int l = 0; l < 32; l++) sum += sP[l * 33 + jj];
            int j = jj >> 1;
            int k = k0 + j;
            float sg = ((j & 2) == 0) ? 1.f : -1.f;   // sigma_j
            if (k <= 511) {
                float fkt = g_kft2[k];
                if (fkt != 0.f)
                    atomicAdd(reinterpret_cast<float*>(g_CS + (size_t)p * KPAD + (k - 1)) + (jj & 1),
                              sum * (sg * fkt));
            }
        }
        __syncthreads();
    }
}

// ---------- forward: packed Clenshaw, direct u64 coefficient loads ----------
__global__ void __launch_bounds__(256) forward_kernel(float* __restrict__ out,
                                                      int M, int P) {
    int m = blockIdx.x * blockDim.x + threadIdx.x;
    if (m >= M) return;
    int hmax = g_hmax;
    if (hmax < 1) return;
    int kmin = g_kmin; if (kmin < 1) kmin = 1;
    int KE  = ((hmax + 1) >> 1) << 1;
    int jlo = ((kmin - 1) >> 1) << 1;
    float fklo = (float)(jlo + 1);
    int p0 = blockIdx.y * PG;
    int p1 = p0 + PG; if (p1 > P) p1 = P;
    const u64p negv = pk2(-1.f, -1.f);

    float total = 0.f;
    int p = p0;
    for (; p + 1 < p1; p += 2) {
        float ba = g_B[(size_t)p * M + m];
        float bb = g_B[(size_t)(p + 1) * M + m];
        float sa, ca, sb, cb;
        __sincosf(TWO_PI_F * ba, &sa, &ca);
        __sincosf(TWO_PI_F * bb, &sb, &cb);
        u64p t2a = pk2(2.f * ca, 2.f * ca);
        u64p t2b = pk2(2.f * cb, 2.f * cb);
        u64p a1 = 0ull, a2 = 0ull, b1 = 0ull, b2 = 0ull;
        const ulonglong2* CA = reinterpret_cast<const ulonglong2*>(g_CS + (size_t)p * KPAD);
        const ulonglong2* CB = reinterpret_cast<const ulonglong2*>(g_CS + (size_t)(p + 1) * KPAD);
#pragma unroll 4
        for (int j = KE - 2; j >= jlo; j -= 2) {
            ulonglong2 fa = __ldg(CA + (j >> 1));   // .x=(C,S)@k=j+1  .y=(C,S)@k=j+2
            ulonglong2 fb = __ldg(CB + (j >> 1));
            u64p ta = fma2(t2a, a1, fa.y);
            u64p na = fma2(negv, a2, ta);
            a2 = a1; a1 = na;
            u64p tb = fma2(t2b, b1, fb.y);
            u64p nb = fma2(negv, b2, tb);
            b2 = b1; b1 = nb;
            ta = fma2(t2a, a1, fa.x);
            na = fma2(negv, a2, ta);
            a2 = a1; a1 = na;
            tb = fma2(t2b, b1, fb.x);
            nb = fma2(negv, b2, tb);
            b2 = b1; b1 = nb;
        }
        {
            float t = fklo * ba;
            float e = fmaf(fklo, ba, -t);
            float f = (t - rintf(t)) + e;
            float sK, cK;
            __sincosf(TWO_PI_F * f, &sK, &cK);
            float cKm = fmaf(cK, ca,  sK * sa);
            float sKm = fmaf(sK, ca, -cK * sa);
            float a1l, a1h, a2l, a2h;
            upk2(a1, a1l, a1h); upk2(a2, a2l, a2h);
            total += fmaf(a1l, cK, -a2l * cKm) + fmaf(a1h, sK, -a2h * sKm);
        }
        {
            float t = fklo * bb;
            float e = fmaf(fklo, bb, -t);
            float f = (t - rintf(t)) + e;
            float sK, cK;
            __sincosf(TWO_PI_F * f, &sK, &cK);
            float cKm = fmaf(cK, cb,  sK * sb);
            float sKm = fmaf(sK, cb, -cK * sb);
            float b1l, b1h, b2l, b2h;
            upk2(b1, b1l, b1h); upk2(b2, b2l, b2h);
            total += fmaf(b1l, cK, -b2l * cKm) + fmaf(b1h, sK, -b2h * sKm);
        }
    }
    if (p < p1) {
        float ba = g_B[(size_t)p * M + m];
        float sa, ca;
        __sincosf(TWO_PI_F * ba, &sa, &ca);
        u64p t2a = pk2(2.f * ca, 2.f * ca);
        u64p a1 = 0ull, a2 = 0ull;
        const ulonglong2* CA = reinterpret_cast<const ulonglong2*>(g_CS + (size_t)p * KPAD);
#pragma unroll 4
        for (int j = KE - 2; j >= jlo; j -= 2) {
            ulonglong2 fa = __ldg(CA + (j >> 1));
            u64p ta = fma2(t2a, a1, fa.y);
            u64p na = fma2(negv, a2, ta);
            a2 = a1; a1 = na;
            ta = fma2(t2a, a1, fa.x);
            na = fma2(negv, a2, ta);
            a2 = a1; a1 = na;
        }
        float t = fklo * ba;
        float e = fmaf(fklo, ba, -t);
        float f = (t - rintf(t)) + e;
        float sK, cK;
        __sincosf(TWO_PI_F * f, &sK, &cK);
        float cKm = fmaf(cK, ca,  sK * sa);
        float sKm = fmaf(sK, ca, -cK * sa);
        float a1l, a1h, a2l, a2h;
        upk2(a1, a1l, a1h); upk2(a2, a2l, a2h);
        total += fmaf(a1l, cK, -a2l * cKm) + fmaf(a1h, sK, -a2h * sKm);
    }
    atomicAdd(out + m, total);
}

extern "C" void kernel_launch(void* const* d_in, const int* in_sizes, int n_in,
                              void* d_out, int out_size) {
    const float* x     = (const float*)d_in[0];
    const float* y     = (const float*)d_in[1];
    const float* w     = (const float*)d_in[2];
    const float* scale = (const float*)d_in[3];
    const float* xis   = (const float*)d_in[4];
    float* out = (float*)d_out;

    int N = in_sizes[2];
    int d = in_sizes[0] / N;
    int M = out_size;
    int P = in_sizes[4] / d;

    int nb = (N + M + 255) / 256;
    if (nb > 256) nb = 256;
    norm_init_kernel<<<nb, 256>>>(x, y, out, N, M, d);
    kft_kernel<<<1, 512>>>(scale, P, (float)d, nb);
    int nmax = (N > M) ? N : M;
    dim3 pgrid((nmax + PROJ_PTS - 1) / PROJ_PTS, 2);
    proj4_kernel<<<pgrid, 256>>>(x, y, xis, N, M, P);
    adjoint_kernel<<<dim3(P, AZ), 256>>>(w, N);
    int ngroups = (P + PG - 1) / PG;
    forward_kernel<<<dim3((M + 255) / 256, ngroups), 256>>>(out, M, P);
}

// round 7
// speedup vs baseline: 1.1162x; 1.1162x over previous
#include <cuda_runtime.h>
#include <math.h>

#define TWO_PI_F  6.28318530717958647692f
#define TWO_PI2_F 19.739208802178716f   /* 2*pi^2 */

#define NMAX 8192
#define PMAX 64
#define KPAD 520
#define ACH 16             /* k per adjoint chunk (multiple of 4!) */
#define AZ 16              /* adjoint N-splits */
#define AE 2               /* elements per adjoint thread */
#define PROJ_PTS 128
#define PG 2               /* slices per forward block */

typedef unsigned long long u64p;

// ---------- packed f32x2 helpers ----------
__device__ __forceinline__ u64p pk2(float lo, float hi) {
    u64p r; asm("mov.b64 %0, {%1, %2};" : "=l"(r) : "f"(lo), "f"(hi)); return r;
}
__device__ __forceinline__ void upk2(u64p v, float& lo, float& hi) {
    asm("mov.b64 {%0, %1}, %2;" : "=f"(lo), "=f"(hi) : "l"(v));
}
__device__ __forceinline__ u64p fma2(u64p a, u64p b, u64p c) {
    u64p d; asm("fma.rn.f32x2 %0, %1, %2, %3;" : "=l"(d) : "l"(a), "l"(b), "l"(c)); return d;
}

// ---------- device scratch ----------
__device__ float  g_A[PMAX * NMAX];    // sf * <x_n, xi_p>, [p][n]
__device__ float  g_B[PMAX * NMAX];    // sf * <y_m, xi_p>, [p][m]
__device__ float2 g_CS[PMAX * KPAD];   // (C*kft2, S*kft2), slot j = k-1
__device__ float  g_kft2[KPAD];        // 2*kft(h)/P, thresholded
__device__ float  g_blockmax[256];
__device__ int    g_hmax;
__device__ int    g_kmin;
__device__ float  g_sf;

// ---------- norm + init fused ----------
__global__ void norm_init_kernel(const float* __restrict__ x, const float* __restrict__ y,
                                 float* __restrict__ out, int N, int M, int d) {
    __shared__ float wmax[8];
    int i = blockIdx.x * blockDim.x + threadIdx.x;
    int stride = gridDim.x * blockDim.x;
    float2 z2 = make_float2(0.f, 0.f);
    for (int j = i; j < PMAX * KPAD; j += stride) g_CS[j] = z2;
    for (int j = i; j < M; j += stride) out[j] = 0.f;
    float v = 0.f;
    int T = N + M;
    if (i < T) {
        const float* row = (i < N) ? (x + (size_t)i * d) : (y + (size_t)(i - N) * d);
        float s = 0.f;
        for (int j = 0; j < d; j += 4) {
            float4 q = *reinterpret_cast<const float4*>(row + j);
            s = fmaf(q.x, q.x, s); s = fmaf(q.y, q.y, s);
            s = fmaf(q.z, q.z, s); s = fmaf(q.w, q.w, s);
        }
        v = s;
    }
#pragma unroll
    for (int off = 16; off > 0; off >>= 1)
        v = fmaxf(v, __shfl_xor_sync(0xffffffffu, v, off));
    if ((threadIdx.x & 31) == 0) wmax[threadIdx.x >> 5] = v;
    __syncthreads();
    if (threadIdx.x == 0) {
        float m = wmax[0];
#pragma unroll
        for (int wq = 1; wq < 8; wq++) m = fmaxf(m, wmax[wq]);
        g_blockmax[blockIdx.x] = m;
    }
}

// ---------- Fourier coefficients, cutoff ----------
__global__ void kft_kernel(const float* __restrict__ scale, int P, float dd, int nb) {
    __shared__ float sred[512];
    int tid = threadIdx.x;
    if (tid == 0) { g_hmax = 0; g_kmin = 0x7fffffff; }
    float bm = (tid < nb) ? g_blockmax[tid] : 0.f;
    sred[tid] = bm;
    __syncthreads();
    for (int s = 256; s > 0; s >>= 1) {
        if (tid < s) sred[tid] = fmaxf(sred[tid], sred[tid + s]);
        __syncthreads();
    }
    float nm = sqrtf(sred[0]);
    float sf = 0.3f / nm;
    float sr = scale[0] * sf;
    float s2 = sr * sr;
    int h = tid + 1;
    float kft = 0.f;
    if (h <= 511) {
        float hp = (float)h;
        float logv = 0.5f * dd * logf(TWO_PI2_F * s2)
                   + (dd - 1.f) * logf(hp)
                   - TWO_PI2_F * s2 * hp * hp
                   - lgammaf(0.5f * dd);
        kft = expf(logv);
    }
    __syncthreads();
    sred[tid] = kft;
    __syncthreads();
    for (int s = 256; s > 0; s >>= 1) {
        if (tid < s) sred[tid] = fmaxf(sred[tid], sred[tid + s]);
        __syncthreads();
    }
    float maxv = sred[0];
    float thr = maxv * 1e-7f;
    bool keep = (h <= 511) && (maxv > 0.f) && (kft > thr);
    if (h <= 511) g_kft2[h] = keep ? kft * (2.f / (float)P) : 0.f;
    if (keep) { atomicMax(&g_hmax, h); atomicMin(&g_kmin, h); }
    if (tid == 0) { g_sf = sf; g_kft2[0] = 0.f; }
    if (tid < 8) g_kft2[512 + tid] = 0.f;
}

// ---------- proj4: smem-staged, full P in one pass, packed fma2 ----------
__global__ void __launch_bounds__(256) proj4_kernel(const float* __restrict__ xpts,
                                                    const float* __restrict__ ypts,
                                                    const float* __restrict__ xis,
                                                    int N, int M, int P) {
    __shared__ float xi_t[64 * 66];
    __shared__ float pts_s[PROJ_PTS * 65];
    int tid = threadIdx.x;
    int which = blockIdx.y;
    const float* pts = which ? ypts : xpts;
    int npts = which ? M : N;
    int base = blockIdx.x * PROJ_PTS;

    for (int idx = tid; idx < 64 * 64; idx += 256) {
        int p = idx >> 6, dc = idx & 63;
        xi_t[dc * 66 + p] = (p < P) ? xis[idx] : 0.f;
    }
    for (int idx = tid; idx < PROJ_PTS * 16; idx += 256) {
        int r = idx >> 4, j4 = idx & 15;
        int n = base + r;
        float4 v = make_float4(0.f, 0.f, 0.f, 0.f);
        if (n < npts) v = *reinterpret_cast<const float4*>(pts + (size_t)n * 64 + j4 * 4);
        float* dp = pts_s + r * 65 + j4 * 4;
        dp[0] = v.x; dp[1] = v.y; dp[2] = v.z; dp[3] = v.w;
    }
    __syncthreads();

    int slot = tid & 63;
    int g = tid >> 6;
    const float* r0 = pts_s + slot * 65;
    const float* r1 = pts_s + (slot + 64) * 65;

    u64p acc0[8], acc1[8];
#pragma unroll
    for (int q = 0; q < 8; q++) { acc0[q] = 0ull; acc1[q] = 0ull; }

#pragma unroll 4
    for (int j = 0; j < 64; j++) {
        float v0 = r0[j], v1 = r1[j];
        u64p vv0 = pk2(v0, v0);
        u64p vv1 = pk2(v1, v1);
        const float* xb = xi_t + j * 66 + g * 16;
#pragma unroll
        for (int q = 0; q < 8; q++) {
            u64p xq = *reinterpret_cast<const u64p*>(xb + 2 * q);
            acc0[q] = fma2(vv0, xq, acc0[q]);
            acc1[q] = fma2(vv1, xq, acc1[q]);
        }
    }

    float sf = g_sf;
    float* dst = which ? g_B : g_A;
    int n0 = base + slot, n1 = n0 + 64;
#pragma unroll
    for (int q = 0; q < 8; q++) {
        float a, b, c, dq;
        upk2(acc0[q], a, b);
        upk2(acc1[q], c, dq);
        int p0 = g * 16 + 2 * q;
        if (p0 < P) {
            if (n0 < npts) dst[(size_t)p0 * npts + n0] = a * sf;
            if (n1 < npts) dst[(size_t)p0 * npts + n1] = c * sf;
        }
        if (p0 + 1 < P) {
            if (n0 < npts) dst[(size_t)(p0 + 1) * npts + n0] = b * sf;
            if (n1 < npts) dst[(size_t)(p0 + 1) * npts + n1] = dq * sf;
        }
    }
}

// ---------- adjoint: chunk-carried Chebyshev + warp reduce-scatter ----------
// Loads + sincos once per element; rotation state carried across chunks.
// Per chunk: 31-shuffle recursive-halving reduce-scatter -> each lane owns one
// (k,comp) sum -> ONE global atomicAdd per lane. No smem, no barriers.
__global__ void __launch_bounds__(256) adjoint_kernel(const float* __restrict__ w, int N) {
    int p = blockIdx.x;
    int z = blockIdx.y;
    int hmax = g_hmax;
    if (hmax < 1) return;
    int klo = g_kmin; if (klo < 1) klo = 1;
    int nchunk = (hmax - klo + ACH) / ACH;

    int tid = threadIdx.x;
    int lane = tid & 31;
    const float* arow = g_A + (size_t)p * N;
    int seg = (N + AZ - 1) / AZ;
    int st = z * seg;
    int en = st + seg; if (en > N) en = N;

    float fklo = (float)klo;
    u64p vc[AE], vp[AE], t2p[AE], nt2p[AE], wp[AE];
#pragma unroll
    for (int e = 0; e < AE; e++) {
        int n = st + tid + e * 256;
        bool ok = (n < en);
        float a  = ok ? arow[n] : 0.f;
        float ww = ok ? w[n]    : 0.f;
        float us, uc;
        __sincosf(TWO_PI_F * a, &us, &uc);
        float t = fklo * a;
        float er = fmaf(fklo, a, -t);
        float f = (t - rintf(t)) + er;
        float zs, zc;
        __sincosf(TWO_PI_F * f, &zs, &zc);
        float zmc = fmaf(zc, uc,  zs * us);   // z_{klo-1} = z_klo * conj(u)
        float zms = fmaf(zs, uc, -zc * us);
        vc[e] = pk2(zc, zs);
        vp[e] = pk2(-zmc, -zms);
        t2p[e]  = pk2( 2.f * uc,  2.f * uc);
        nt2p[e] = pk2(-2.f * uc, -2.f * uc);
        wp[e] = pk2(ww, ww);
    }

    for (int c = 0; c < nchunk; c++) {
        int k0 = klo + c * ACH;
        u64p accv[ACH];
#pragma unroll
        for (int j = 0; j < ACH; j++) accv[j] = 0ull;

#pragma unroll
        for (int j = 0; j < ACH; j++) {
#pragma unroll
            for (int e = 0; e < AE; e++) {
                accv[j] = fma2(wp[e], vc[e], accv[j]);
                u64p vn = fma2((j & 1) ? nt2p[e] : t2p[e], vc[e], vp[e]);
                vp[e] = vc[e]; vc[e] = vn;
            }
        }

        // unpack: a[2j]=C_j, a[2j+1]=S_j
        float a[2 * ACH];
#pragma unroll
        for (int j = 0; j < ACH; j++) upk2(accv[j], a[2 * j], a[2 * j + 1]);

        // recursive-halving reduce-scatter: lane l ends owning index l
#pragma unroll
        for (int B = 16; B >= 1; B >>= 1) {
            bool bit = (lane & B) != 0;
#pragma unroll
            for (int i = 0; i < B; i++) {
                float snd = bit ? a[i] : a[i + B];
                float kp  = bit ? a[i + B] : a[i];
                a[i] = kp + __shfl_xor_sync(0xffffffffu, snd, B);
            }
        }

        int j = lane >> 1;
        int k = k0 + j;
        float sg = ((j & 2) == 0) ? 1.f : -1.f;   // sigma_j
        if (k <= 511) {
            float fkt = g_kft2[k];
            if (fkt != 0.f)
                atomicAdd(reinterpret_cast<float*>(g_CS + (size_t)p * KPAD + (k - 1)) + (lane & 1),
                          a[0] * (sg * fkt));
        }
    }
}

// ---------- forward helpers ----------
__device__ __forceinline__ void clenshaw_step(u64p& b1, u64p& b2, u64p t2, u64p negv, u64p coef) {
    u64p t = fma2(t2, b1, coef);
    u64p n = fma2(negv, b2, t);
    b2 = b1; b1 = n;
}
__device__ __forceinline__ float clenshaw_fin(u64p b1, u64p b2, float fk0,
                                              float bv, float cu, float su) {
    float t = fk0 * bv;
    float e = fmaf(fk0, bv, -t);
    float f = (t - rintf(t)) + e;
    float sK, cK;
    __sincosf(TWO_PI_F * f, &sK, &cK);
    float cKm = fmaf(cK, cu,  sK * su);
    float sKm = fmaf(sK, cu, -cK * su);
    float b1l, b1h, b2l, b2h;
    upk2(b1, b1l, b1h); upk2(b2, b2l, b2h);
    return fmaf(b1l, cK, -b2l * cKm) + fmaf(b1h, sK, -b2h * sKm);
}

// ---------- forward: split-range packed Clenshaw (2 halves x 2 slices = 4 chains) ----------
__global__ void __launch_bounds__(256) forward_kernel(float* __restrict__ out,
                                                      int M, int P) {
    int m = blockIdx.x * blockDim.x + threadIdx.x;
    if (m >= M) return;
    int hmax = g_hmax;
    if (hmax < 1) return;
    int kmin = g_kmin; if (kmin < 1) kmin = 1;
    int KE  = ((hmax + 1) >> 1) << 1;
    int jlo = ((kmin - 1) >> 1) << 1;
    int T = (KE - jlo) >> 1;        // coefficient pairs
    int L = (T + 1) >> 1;           // iters per half (upper padded into zero slots)
    int idx0 = jlo >> 1;            // base pair index
    float fklo = (float)(jlo + 1);
    float fkhi = (float)(jlo + 2 * L + 1);
    const u64p negv = pk2(-1.f, -1.f);

    int p0 = blockIdx.y * PG;
    float total = 0.f;

    if (p0 + 1 < P) {
        float ba = g_B[(size_t)p0 * M + m];
        float bb = g_B[(size_t)(p0 + 1) * M + m];
        float sa, ca, sb, cb;
        __sincosf(TWO_PI_F * ba, &sa, &ca);
        __sincosf(TWO_PI_F * bb, &sb, &cb);
        u64p t2a = pk2(2.f * ca, 2.f * ca);
        u64p t2b = pk2(2.f * cb, 2.f * cb);
        u64p a1 = 0ull, a2 = 0ull, h1 = 0ull, h2 = 0ull;
        u64p b1 = 0ull, b2 = 0ull, g1 = 0ull, g2 = 0ull;
        const ulonglong2* CA = reinterpret_cast<const ulonglong2*>(g_CS + (size_t)p0 * KPAD);
        const ulonglong2* CB = reinterpret_cast<const ulonglong2*>(g_CS + (size_t)(p0 + 1) * KPAD);
#pragma unroll 2
        for (int i = L - 1; i >= 0; i--) {
            ulonglong2 fa  = __ldg(CA + idx0 + i);       // lower half, slices a
            ulonglong2 fah = __ldg(CA + idx0 + L + i);   // upper half
            ulonglong2 fb  = __ldg(CB + idx0 + i);
            ulonglong2 fbh = __ldg(CB + idx0 + L + i);
            clenshaw_step(a1, a2, t2a, negv, fa.y);
            clenshaw_step(h1, h2, t2a, negv, fah.y);
            clenshaw_step(b1, b2, t2b, negv, fb.y);
            clenshaw_step(g1, g2, t2b, negv, fbh.y);
            clenshaw_step(a1, a2, t2a, negv, fa.x);
            clenshaw_step(h1, h2, t2a, negv, fah.x);
            clenshaw_step(b1, b2, t2b, negv, fb.x);
            clenshaw_step(g1, g2, t2b, negv, fbh.x);
        }
        total += clenshaw_fin(a1, a2, fklo, ba, ca, sa);
        total += clenshaw_fin(h1, h2, fkhi, ba, ca, sa);
        total += clenshaw_fin(b1, b2, fklo, bb, cb, sb);
        total += clenshaw_fin(g1, g2, fkhi, bb, cb, sb);
    } else if (p0 < P) {   // odd-P tail: single slice, two halves
        float ba = g_B[(size_t)p0 * M + m];
        float sa, ca;
        __sincosf(TWO_PI_F * ba, &sa, &ca);
        u64p t2a = pk2(2.f * ca, 2.f * ca);
        u64p a1 = 0ull, a2 = 0ull, h1 = 0ull, h2 = 0ull;
        const ulonglong2* CA = reinterpret_cast<const ulonglong2*>(g_CS + (size_t)p0 * KPAD);
#pragma unroll 2
        for (int i = L - 1; i >= 0; i--) {
            ulonglong2 fa  = __ldg(CA + idx0 + i);
            ulonglong2 fah = __ldg(CA + idx0 + L + i);
            clenshaw_step(a1, a2, t2a, negv, fa.y);
            clenshaw_step(h1, h2, t2a, negv, fah.y);
            clenshaw_step(a1, a2, t2a, negv, fa.x);
            clenshaw_step(h1, h2, t2a, negv, fah.x);
        }
        total += clenshaw_fin(a1, a2, fklo, ba, ca, sa);
        total += clenshaw_fin(h1, h2, fkhi, ba, ca, sa);
    }
    atomicAdd(out + m, total);
}

extern "C" void kernel_launch(void* const* d_in, const int* in_sizes, int n_in,
                              void* d_out, int out_size) {
    const float* x     = (const float*)d_in[0];
    const float* y     = (const float*)d_in[1];
    const float* w     = (const float*)d_in[2];
    const float* scale = (const float*)d_in[3];
    const float* xis   = (const float*)d_in[4];
    float* out = (float*)d_out;

    int N = in_sizes[2];
    int d = in_sizes[0] / N;
    int M = out_size;
    int P = in_sizes[4] / d;

    int nb = (N + M + 255) / 256;
    if (nb > 256) nb = 256;
    norm_init_kernel<<<nb, 256>>>(x, y, out, N, M, d);
    kft_kernel<<<1, 512>>>(scale, P, (float)d, nb);
    int nmax = (N > M) ? N : M;
    dim3 pgrid((nmax + PROJ_PTS - 1) / PROJ_PTS, 2);
    proj4_kernel<<<pgrid, 256>>>(x, y, xis, N, M, P);
    adjoint_kernel<<<dim3(P, AZ), 256>>>(w, N);
    int ngroups = (P + PG - 1) / PG;
    forward_kernel<<<dim3((M + 255) / 256, ngroups), 256>>>(out, M, P);
}

// round 8
// speedup vs baseline: 1.2098x; 1.0839x over previous
#include <cuda_runtime.h>
#include <math.h>

#define TWO_PI_F  6.28318530717958647692f
#define TWO_PI2_F 19.739208802178716f   /* 2*pi^2 */

#define NMAX 8192
#define PMAX 64
#define KPAD 520
#define ACH 16             /* k per adjoint chunk (multiple of 4!) */
#define AZ 8               /* adjoint N-splits */
#define AE 4               /* elements per adjoint thread */
#define PROJ_PTS 128
#define PG 2               /* slices per forward block */

typedef unsigned long long u64p;

// ---------- packed f32x2 helpers ----------
__device__ __forceinline__ u64p pk2(float lo, float hi) {
    u64p r; asm("mov.b64 %0, {%1, %2};" : "=l"(r) : "f"(lo), "f"(hi)); return r;
}
__device__ __forceinline__ void upk2(u64p v, float& lo, float& hi) {
    asm("mov.b64 {%0, %1}, %2;" : "=f"(lo), "=f"(hi) : "l"(v));
}
__device__ __forceinline__ u64p fma2(u64p a, u64p b, u64p c) {
    u64p d; asm("fma.rn.f32x2 %0, %1, %2, %3;" : "=l"(d) : "l"(a), "l"(b), "l"(c)); return d;
}

// ---------- device scratch ----------
__device__ float  g_A[PMAX * NMAX];    // sf * <x_n, xi_p>, [p][n]
__device__ float  g_B[PMAX * NMAX];    // sf * <y_m, xi_p>, [p][m]
__device__ float2 g_CS[PMAX * KPAD];   // (C*kft2, S*kft2), slot j = k-1
__device__ float  g_kft2[KPAD];        // 2*kft(h)/P, thresholded
__device__ float  g_blockmax[256];
__device__ int    g_hmax;
__device__ int    g_kmin;
__device__ float  g_sf;

// ---------- norm + init fused ----------
__global__ void norm_init_kernel(const float* __restrict__ x, const float* __restrict__ y,
                                 float* __restrict__ out, int N, int M, int d) {
    __shared__ float wmax[8];
    int i = blockIdx.x * blockDim.x + threadIdx.x;
    int stride = gridDim.x * blockDim.x;
    float2 z2 = make_float2(0.f, 0.f);
    for (int j = i; j < PMAX * KPAD; j += stride) g_CS[j] = z2;
    for (int j = i; j < M; j += stride) out[j] = 0.f;
    float v = 0.f;
    int T = N + M;
    if (i < T) {
        const float* row = (i < N) ? (x + (size_t)i * d) : (y + (size_t)(i - N) * d);
        float s = 0.f;
        for (int j = 0; j < d; j += 4) {
            float4 q = *reinterpret_cast<const float4*>(row + j);
            s = fmaf(q.x, q.x, s); s = fmaf(q.y, q.y, s);
            s = fmaf(q.z, q.z, s); s = fmaf(q.w, q.w, s);
        }
        v = s;
    }
#pragma unroll
    for (int off = 16; off > 0; off >>= 1)
        v = fmaxf(v, __shfl_xor_sync(0xffffffffu, v, off));
    if ((threadIdx.x & 31) == 0) wmax[threadIdx.x >> 5] = v;
    __syncthreads();
    if (threadIdx.x == 0) {
        float m = wmax[0];
#pragma unroll
        for (int wq = 1; wq < 8; wq++) m = fmaxf(m, wmax[wq]);
        g_blockmax[blockIdx.x] = m;
    }
}

// ---------- Fourier coefficients, cutoff ----------
__global__ void kft_kernel(const float* __restrict__ scale, int P, float dd, int nb) {
    __shared__ float sred[512];
    int tid = threadIdx.x;
    if (tid == 0) { g_hmax = 0; g_kmin = 0x7fffffff; }
    float bm = (tid < nb) ? g_blockmax[tid] : 0.f;
    sred[tid] = bm;
    __syncthreads();
    for (int s = 256; s > 0; s >>= 1) {
        if (tid < s) sred[tid] = fmaxf(sred[tid], sred[tid + s]);
        __syncthreads();
    }
    float nm = sqrtf(sred[0]);
    float sf = 0.3f / nm;
    float sr = scale[0] * sf;
    float s2 = sr * sr;
    int h = tid + 1;
    float kft = 0.f;
    if (h <= 511) {
        float hp = (float)h;
        float logv = 0.5f * dd * logf(TWO_PI2_F * s2)
                   + (dd - 1.f) * logf(hp)
                   - TWO_PI2_F * s2 * hp * hp
                   - lgammaf(0.5f * dd);
        kft = expf(logv);
    }
    __syncthreads();
    sred[tid] = kft;
    __syncthreads();
    for (int s = 256; s > 0; s >>= 1) {
        if (tid < s) sred[tid] = fmaxf(sred[tid], sred[tid + s]);
        __syncthreads();
    }
    float maxv = sred[0];
    float thr = maxv * 1e-7f;
    bool keep = (h <= 511) && (maxv > 0.f) && (kft > thr);
    if (h <= 511) g_kft2[h] = keep ? kft * (2.f / (float)P) : 0.f;
    if (keep) { atomicMax(&g_hmax, h); atomicMin(&g_kmin, h); }
    if (tid == 0) { g_sf = sf; g_kft2[0] = 0.f; }
    if (tid < 8) g_kft2[512 + tid] = 0.f;
}

// ---------- proj4: smem-staged, full P in one pass, packed fma2 ----------
__global__ void __launch_bounds__(256) proj4_kernel(const float* __restrict__ xpts,
                                                    const float* __restrict__ ypts,
                                                    const float* __restrict__ xis,
                                                    int N, int M, int P) {
    __shared__ float xi_t[64 * 66];
    __shared__ float pts_s[PROJ_PTS * 68];   // row stride 68 (16B aligned, conflict-free)
    int tid = threadIdx.x;
    int which = blockIdx.y;
    const float* pts = which ? ypts : xpts;
    int npts = which ? M : N;
    int base = blockIdx.x * PROJ_PTS;

    for (int idx = tid; idx < 64 * 64; idx += 256) {
        int p = idx >> 6, dc = idx & 63;
        xi_t[dc * 66 + p] = (p < P) ? xis[idx] : 0.f;
    }
    for (int idx = tid; idx < PROJ_PTS * 16; idx += 256) {
        int r = idx >> 4, j4 = idx & 15;
        int n = base + r;
        float4 v = make_float4(0.f, 0.f, 0.f, 0.f);
        if (n < npts) v = *reinterpret_cast<const float4*>(pts + (size_t)n * 64 + j4 * 4);
        *reinterpret_cast<float4*>(pts_s + r * 68 + j4 * 4) = v;
    }
    __syncthreads();

    int slot = tid & 63;
    int g = tid >> 6;
    const float4* r0 = reinterpret_cast<const float4*>(pts_s + slot * 68);
    const float4* r1 = reinterpret_cast<const float4*>(pts_s + (slot + 64) * 68);

    u64p acc0[8], acc1[8];
#pragma unroll
    for (int q = 0; q < 8; q++) { acc0[q] = 0ull; acc1[q] = 0ull; }

#pragma unroll
    for (int j4 = 0; j4 < 16; j4++) {
        float4 v0 = r0[j4];
        float4 v1 = r1[j4];
#pragma unroll
        for (int s = 0; s < 4; s++) {
            float f0 = (s == 0) ? v0.x : (s == 1) ? v0.y : (s == 2) ? v0.z : v0.w;
            float f1 = (s == 0) ? v1.x : (s == 1) ? v1.y : (s == 2) ? v1.z : v1.w;
            u64p vv0 = pk2(f0, f0);
            u64p vv1 = pk2(f1, f1);
            const float* xb = xi_t + (j4 * 4 + s) * 66 + g * 16;
#pragma unroll
            for (int q = 0; q < 8; q++) {
                u64p xq = *reinterpret_cast<const u64p*>(xb + 2 * q);
                acc0[q] = fma2(vv0, xq, acc0[q]);
                acc1[q] = fma2(vv1, xq, acc1[q]);
            }
        }
    }

    float sf = g_sf;
    float* dst = which ? g_B : g_A;
    int n0 = base + slot, n1 = n0 + 64;
#pragma unroll
    for (int q = 0; q < 8; q++) {
        float a, b, c, dq;
        upk2(acc0[q], a, b);
        upk2(acc1[q], c, dq);
        int p0 = g * 16 + 2 * q;
        if (p0 < P) {
            if (n0 < npts) dst[(size_t)p0 * npts + n0] = a * sf;
            if (n1 < npts) dst[(size_t)p0 * npts + n1] = c * sf;
        }
        if (p0 + 1 < P) {
            if (n0 < npts) dst[(size_t)(p0 + 1) * npts + n0] = b * sf;
            if (n1 < npts) dst[(size_t)(p0 + 1) * npts + n1] = dq * sf;
        }
    }
}

// ---------- adjoint: chunk-carried Chebyshev + warp reduce-scatter, AE=4 ----------
__global__ void __launch_bounds__(256) adjoint_kernel(const float* __restrict__ w, int N) {
    int p = blockIdx.x;
    int z = blockIdx.y;
    int hmax = g_hmax;
    if (hmax < 1) return;
    int klo = g_kmin; if (klo < 1) klo = 1;
    int nchunk = (hmax - klo + ACH) / ACH;

    int tid = threadIdx.x;
    int lane = tid & 31;
    const float* arow = g_A + (size_t)p * N;
    int seg = (N + AZ - 1) / AZ;
    int st = z * seg;
    int en = st + seg; if (en > N) en = N;

    float fklo = (float)klo;
    u64p vc[AE], vp[AE], t2p[AE], nt2p[AE], wp[AE];
#pragma unroll
    for (int e = 0; e < AE; e++) {
        int n = st + tid + e * 256;
        bool ok = (n < en);
        float a  = ok ? arow[n] : 0.f;
        float ww = ok ? w[n]    : 0.f;
        float us, uc;
        __sincosf(TWO_PI_F * a, &us, &uc);
        float t = fklo * a;
        float er = fmaf(fklo, a, -t);
        float f = (t - rintf(t)) + er;
        float zs, zc;
        __sincosf(TWO_PI_F * f, &zs, &zc);
        float zmc = fmaf(zc, uc,  zs * us);   // z_{klo-1} = z_klo * conj(u)
        float zms = fmaf(zs, uc, -zc * us);
        vc[e] = pk2(zc, zs);
        vp[e] = pk2(-zmc, -zms);
        t2p[e]  = pk2( 2.f * uc,  2.f * uc);
        nt2p[e] = pk2(-2.f * uc, -2.f * uc);
        wp[e] = pk2(ww, ww);
    }

    for (int c = 0; c < nchunk; c++) {
        int k0 = klo + c * ACH;
        u64p accv[ACH];
#pragma unroll
        for (int j = 0; j < ACH; j++) accv[j] = 0ull;

#pragma unroll
        for (int j = 0; j < ACH; j++) {
#pragma unroll
            for (int e = 0; e < AE; e++) {
                accv[j] = fma2(wp[e], vc[e], accv[j]);
                u64p vn = fma2((j & 1) ? nt2p[e] : t2p[e], vc[e], vp[e]);
                vp[e] = vc[e]; vc[e] = vn;
            }
        }

        // unpack: a[2j]=C_j, a[2j+1]=S_j
        float a[2 * ACH];
#pragma unroll
        for (int j = 0; j < ACH; j++) upk2(accv[j], a[2 * j], a[2 * j + 1]);

        // recursive-halving reduce-scatter: lane l ends owning index l
#pragma unroll
        for (int B = 16; B >= 1; B >>= 1) {
            bool bit = (lane & B) != 0;
#pragma unroll
            for (int i = 0; i < B; i++) {
                float snd = bit ? a[i] : a[i + B];
                float kp  = bit ? a[i + B] : a[i];
                a[i] = kp + __shfl_xor_sync(0xffffffffu, snd, B);
            }
        }

        int j = lane >> 1;
        int k = k0 + j;
        float sg = ((j & 2) == 0) ? 1.f : -1.f;   // sigma_j
        if (k <= 511) {
            float fkt = g_kft2[k];
            if (fkt != 0.f)
                atomicAdd(reinterpret_cast<float*>(g_CS + (size_t)p * KPAD + (k - 1)) + (lane & 1),
                          a[0] * (sg * fkt));
        }
    }
}

// ---------- forward helpers ----------
__device__ __forceinline__ void clenshaw_step(u64p& b1, u64p& b2, u64p t2, u64p negv, u64p coef) {
    u64p t = fma2(t2, b1, coef);
    u64p n = fma2(negv, b2, t);
    b2 = b1; b1 = n;
}
__device__ __forceinline__ float clenshaw_fin(u64p b1, u64p b2, float fk0,
                                              float bv, float cu, float su) {
    float t = fk0 * bv;
    float e = fmaf(fk0, bv, -t);
    float f = (t - rintf(t)) + e;
    float sK, cK;
    __sincosf(TWO_PI_F * f, &sK, &cK);
    float cKm = fmaf(cK, cu,  sK * su);
    float sKm = fmaf(sK, cu, -cK * su);
    float b1l, b1h, b2l, b2h;
    upk2(b1, b1l, b1h); upk2(b2, b2l, b2h);
    return fmaf(b1l, cK, -b2l * cKm) + fmaf(b1h, sK, -b2h * sKm);
}

// ---------- forward: split-range packed Clenshaw (2 halves x 2 slices = 4 chains) ----------
__global__ void __launch_bounds__(256) forward_kernel(float* __restrict__ out,
                                                      int M, int P) {
    int m = blockIdx.x * blockDim.x + threadIdx.x;
    if (m >= M) return;
    int hmax = g_hmax;
    if (hmax < 1) return;
    int kmin = g_kmin; if (kmin < 1) kmin = 1;
    int KE  = ((hmax + 1) >> 1) << 1;
    int jlo = ((kmin - 1) >> 1) << 1;
    int T = (KE - jlo) >> 1;        // coefficient pairs
    int L = (T + 1) >> 1;           // iters per half (upper padded into zero slots)
    int idx0 = jlo >> 1;            // base pair index
    float fklo = (float)(jlo + 1);
    float fkhi = (float)(jlo + 2 * L + 1);
    const u64p negv = pk2(-1.f, -1.f);

    int p0 = blockIdx.y * PG;
    float total = 0.f;

    if (p0 + 1 < P) {
        float ba = g_B[(size_t)p0 * M + m];
        float bb = g_B[(size_t)(p0 + 1) * M + m];
        float sa, ca, sb, cb;
        __sincosf(TWO_PI_F * ba, &sa, &ca);
        __sincosf(TWO_PI_F * bb, &sb, &cb);
        u64p t2a = pk2(2.f * ca, 2.f * ca);
        u64p t2b = pk2(2.f * cb, 2.f * cb);
        u64p a1 = 0ull, a2 = 0ull, h1 = 0ull, h2 = 0ull;
        u64p b1 = 0ull, b2 = 0ull, g1 = 0ull, g2 = 0ull;
        const ulonglong2* CA = reinterpret_cast<const ulonglong2*>(g_CS + (size_t)p0 * KPAD);
        const ulonglong2* CB = reinterpret_cast<const ulonglong2*>(g_CS + (size_t)(p0 + 1) * KPAD);
#pragma unroll 2
        for (int i = L - 1; i >= 0; i--) {
            ulonglong2 fa  = __ldg(CA + idx0 + i);
            ulonglong2 fah = __ldg(CA + idx0 + L + i);
            ulonglong2 fb  = __ldg(CB + idx0 + i);
            ulonglong2 fbh = __ldg(CB + idx0 + L + i);
            clenshaw_step(a1, a2, t2a, negv, fa.y);
            clenshaw_step(h1, h2, t2a, negv, fah.y);
            clenshaw_step(b1, b2, t2b, negv, fb.y);
            clenshaw_step(g1, g2, t2b, negv, fbh.y);
            clenshaw_step(a1, a2, t2a, negv, fa.x);
            clenshaw_step(h1, h2, t2a, negv, fah.x);
            clenshaw_step(b1, b2, t2b, negv, fb.x);
            clenshaw_step(g1, g2, t2b, negv, fbh.x);
        }
        total += clenshaw_fin(a1, a2, fklo, ba, ca, sa);
        total += clenshaw_fin(h1, h2, fkhi, ba, ca, sa);
        total += clenshaw_fin(b1, b2, fklo, bb, cb, sb);
        total += clenshaw_fin(g1, g2, fkhi, bb, cb, sb);
    } else if (p0 < P) {   // odd-P tail
        float ba = g_B[(size_t)p0 * M + m];
        float sa, ca;
        __sincosf(TWO_PI_F * ba, &sa, &ca);
        u64p t2a = pk2(2.f * ca, 2.f * ca);
        u64p a1 = 0ull, a2 = 0ull, h1 = 0ull, h2 = 0ull;
        const ulonglong2* CA = reinterpret_cast<const ulonglong2*>(g_CS + (size_t)p0 * KPAD);
#pragma unroll 2
        for (int i = L - 1; i >= 0; i--) {
            ulonglong2 fa  = __ldg(CA + idx0 + i);
            ulonglong2 fah = __ldg(CA + idx0 + L + i);
            clenshaw_step(a1, a2, t2a, negv, fa.y);
            clenshaw_step(h1, h2, t2a, negv, fah.y);
            clenshaw_step(a1, a2, t2a, negv, fa.x);
            clenshaw_step(h1, h2, t2a, negv, fah.x);
        }
        total += clenshaw_fin(a1, a2, fklo, ba, ca, sa);
        total += clenshaw_fin(h1, h2, fkhi, ba, ca, sa);
    }
    atomicAdd(out + m, total);
}

extern "C" void kernel_launch(void* const* d_in, const int* in_sizes, int n_in,
                              void* d_out, int out_size) {
    const float* x     = (const float*)d_in[0];
    const float* y     = (const float*)d_in[1];
    const float* w     = (const float*)d_in[2];
    const float* scale = (const float*)d_in[3];
    const float* xis   = (const float*)d_in[4];
    float* out = (float*)d_out;

    int N = in_sizes[2];
    int d = in_sizes[0] / N;
    int M = out_size;
    int P = in_sizes[4] / d;

    int nb = (N + M + 255) / 256;
    if (nb > 256) nb = 256;
    norm_init_kernel<<<nb, 256>>>(x, y, out, N, M, d);
    kft_kernel<<<1, 512>>>(scale, P, (float)d, nb);
    int nmax = (N > M) ? N : M;
    dim3 pgrid((nmax + PROJ_PTS - 1) / PROJ_PTS, 2);
    proj4_kernel<<<pgrid, 256>>>(x, y, xis, N, M, P);
    adjoint_kernel<<<dim3(P, AZ), 256>>>(w, N);
    int ngroups = (P + PG - 1) / PG;
    forward_kernel<<<dim3((M + 255) / 256, ngroups), 256>>>(out, M, P);
}

// round 9
// speedup vs baseline: 1.2177x; 1.0065x over previous
#include <cuda_runtime.h>
#include <math.h>

#define TWO_PI_F  6.28318530717958647692f
#define TWO_PI2_F 19.739208802178716f   /* 2*pi^2 */

#define NMAX 8192
#define PMAX 64
#define KPAD 520
#define ACH 16             /* k per adjoint chunk (multiple of 4!) */
#define AZ 8               /* adjoint N-splits */
#define AE 8               /* elements per adjoint thread */
#define ABLK 128           /* adjoint block size */
#define PROJ_PTS 128
#define PG 2               /* slices per forward block */

typedef unsigned long long u64p;

// ---------- packed f32x2 helpers ----------
__device__ __forceinline__ u64p pk2(float lo, float hi) {
    u64p r; asm("mov.b64 %0, {%1, %2};" : "=l"(r) : "f"(lo), "f"(hi)); return r;
}
__device__ __forceinline__ void upk2(u64p v, float& lo, float& hi) {
    asm("mov.b64 {%0, %1}, %2;" : "=f"(lo), "=f"(hi) : "l"(v));
}
__device__ __forceinline__ u64p fma2(u64p a, u64p b, u64p c) {
    u64p d; asm("fma.rn.f32x2 %0, %1, %2, %3;" : "=l"(d) : "l"(a), "l"(b), "l"(c)); return d;
}

// ---------- device scratch ----------
__device__ float  g_A[PMAX * NMAX];    // sf * <x_n, xi_p>, [p][n]
__device__ float  g_B[PMAX * NMAX];    // sf * <y_m, xi_p>, [p][m]
__device__ float2 g_CS[PMAX * KPAD];   // (C*kft2, S*kft2), slot j = k-1
__device__ float  g_kft2[KPAD];        // 2*kft(h)/P, thresholded
__device__ float  g_blockmax[256];
__device__ int    g_hmax;
__device__ int    g_kmin;
__device__ float  g_sf;

// ---------- norm + init fused ----------
__global__ void norm_init_kernel(const float* __restrict__ x, const float* __restrict__ y,
                                 float* __restrict__ out, int N, int M, int d) {
    __shared__ float wmax[8];
    int i = blockIdx.x * blockDim.x + threadIdx.x;
    int stride = gridDim.x * blockDim.x;
    float2 z2 = make_float2(0.f, 0.f);
    for (int j = i; j < PMAX * KPAD; j += stride) g_CS[j] = z2;
    for (int j = i; j < M; j += stride) out[j] = 0.f;
    float v = 0.f;
    int T = N + M;
    if (i < T) {
        const float* row = (i < N) ? (x + (size_t)i * d) : (y + (size_t)(i - N) * d);
        float s = 0.f;
        for (int j = 0; j < d; j += 4) {
            float4 q = *reinterpret_cast<const float4*>(row + j);
            s = fmaf(q.x, q.x, s); s = fmaf(q.y, q.y, s);
            s = fmaf(q.z, q.z, s); s = fmaf(q.w, q.w, s);
        }
        v = s;
    }
#pragma unroll
    for (int off = 16; off > 0; off >>= 1)
        v = fmaxf(v, __shfl_xor_sync(0xffffffffu, v, off));
    if ((threadIdx.x & 31) == 0) wmax[threadIdx.x >> 5] = v;
    __syncthreads();
    if (threadIdx.x == 0) {
        float m = wmax[0];
#pragma unroll
        for (int wq = 1; wq < 8; wq++) m = fmaxf(m, wmax[wq]);
        g_blockmax[blockIdx.x] = m;
    }
}

// ---------- Fourier coefficients, cutoff ----------
__global__ void kft_kernel(const float* __restrict__ scale, int P, float dd, int nb) {
    __shared__ float sred[512];
    int tid = threadIdx.x;
    if (tid == 0) { g_hmax = 0; g_kmin = 0x7fffffff; }
    float bm = (tid < nb) ? g_blockmax[tid] : 0.f;
    sred[tid] = bm;
    __syncthreads();
    for (int s = 256; s > 0; s >>= 1) {
        if (tid < s) sred[tid] = fmaxf(sred[tid], sred[tid + s]);
        __syncthreads();
    }
    float nm = sqrtf(sred[0]);
    float sf = 0.3f / nm;
    float sr = scale[0] * sf;
    float s2 = sr * sr;
    int h = tid + 1;
    float kft = 0.f;
    if (h <= 511) {
        float hp = (float)h;
        float logv = 0.5f * dd * logf(TWO_PI2_F * s2)
                   + (dd - 1.f) * logf(hp)
                   - TWO_PI2_F * s2 * hp * hp
                   - lgammaf(0.5f * dd);
        kft = expf(logv);
    }
    __syncthreads();
    sred[tid] = kft;
    __syncthreads();
    for (int s = 256; s > 0; s >>= 1) {
        if (tid < s) sred[tid] = fmaxf(sred[tid], sred[tid + s]);
        __syncthreads();
    }
    float maxv = sred[0];
    float thr = maxv * 1e-7f;
    bool keep = (h <= 511) && (maxv > 0.f) && (kft > thr);
    if (h <= 511) g_kft2[h] = keep ? kft * (2.f / (float)P) : 0.f;
    if (keep) { atomicMax(&g_hmax, h); atomicMin(&g_kmin, h); }
    if (tid == 0) { g_sf = sf; g_kft2[0] = 0.f; }
    if (tid < 8) g_kft2[512 + tid] = 0.f;
}

// ---------- proj4: smem-staged, full P in one pass, packed fma2 ----------
__global__ void __launch_bounds__(256) proj4_kernel(const float* __restrict__ xpts,
                                                    const float* __restrict__ ypts,
                                                    const float* __restrict__ xis,
                                                    int N, int M, int P) {
    __shared__ float xi_t[64 * 66];
    __shared__ float pts_s[PROJ_PTS * 68];   // row stride 68 (16B aligned, conflict-free)
    int tid = threadIdx.x;
    int which = blockIdx.y;
    const float* pts = which ? ypts : xpts;
    int npts = which ? M : N;
    int base = blockIdx.x * PROJ_PTS;

    for (int idx = tid; idx < 64 * 64; idx += 256) {
        int p = idx >> 6, dc = idx & 63;
        xi_t[dc * 66 + p] = (p < P) ? xis[idx] : 0.f;
    }
    for (int idx = tid; idx < PROJ_PTS * 16; idx += 256) {
        int r = idx >> 4, j4 = idx & 15;
        int n = base + r;
        float4 v = make_float4(0.f, 0.f, 0.f, 0.f);
        if (n < npts) v = *reinterpret_cast<const float4*>(pts + (size_t)n * 64 + j4 * 4);
        *reinterpret_cast<float4*>(pts_s + r * 68 + j4 * 4) = v;
    }
    __syncthreads();

    int slot = tid & 63;
    int g = tid >> 6;
    const float4* r0 = reinterpret_cast<const float4*>(pts_s + slot * 68);
    const float4* r1 = reinterpret_cast<const float4*>(pts_s + (slot + 64) * 68);

    u64p acc0[8], acc1[8];
#pragma unroll
    for (int q = 0; q < 8; q++) { acc0[q] = 0ull; acc1[q] = 0ull; }

#pragma unroll
    for (int j4 = 0; j4 < 16; j4++) {
        float4 v0 = r0[j4];
        float4 v1 = r1[j4];
#pragma unroll
        for (int s = 0; s < 4; s++) {
            float f0 = (s == 0) ? v0.x : (s == 1) ? v0.y : (s == 2) ? v0.z : v0.w;
            float f1 = (s == 0) ? v1.x : (s == 1) ? v1.y : (s == 2) ? v1.z : v1.w;
            u64p vv0 = pk2(f0, f0);
            u64p vv1 = pk2(f1, f1);
            const float* xb = xi_t + (j4 * 4 + s) * 66 + g * 16;
#pragma unroll
            for (int q = 0; q < 8; q++) {
                u64p xq = *reinterpret_cast<const u64p*>(xb + 2 * q);
                acc0[q] = fma2(vv0, xq, acc0[q]);
                acc1[q] = fma2(vv1, xq, acc1[q]);
            }
        }
    }

    float sf = g_sf;
    float* dst = which ? g_B : g_A;
    int n0 = base + slot, n1 = n0 + 64;
#pragma unroll
    for (int q = 0; q < 8; q++) {
        float a, b, c, dq;
        upk2(acc0[q], a, b);
        upk2(acc1[q], c, dq);
        int p0 = g * 16 + 2 * q;
        if (p0 < P) {
            if (n0 < npts) dst[(size_t)p0 * npts + n0] = a * sf;
            if (n1 < npts) dst[(size_t)p0 * npts + n1] = c * sf;
        }
        if (p0 + 1 < P) {
            if (n0 < npts) dst[(size_t)(p0 + 1) * npts + n0] = b * sf;
            if (n1 < npts) dst[(size_t)(p0 + 1) * npts + n1] = dq * sf;
        }
    }
}

// ---------- adjoint: chunk-carried Chebyshev + warp reduce-scatter, AE=8 ----------
// block=128, AE=8 -> 2048 total warps: halves the (per-warp) reduce-scatter and
// prologue cost vs AE=4/256. Rotation has 8 independent chains -> 16 independent
// fma2 per dependency step, so low occupancy still saturates issue.
__global__ void __launch_bounds__(ABLK) adjoint_kernel(const float* __restrict__ w, int N) {
    int p = blockIdx.x;
    int z = blockIdx.y;
    int hmax = g_hmax;
    if (hmax < 1) return;
    int klo = g_kmin; if (klo < 1) klo = 1;
    int nchunk = (hmax - klo + ACH) / ACH;

    int tid = threadIdx.x;
    int lane = tid & 31;
    const float* arow = g_A + (size_t)p * N;
    int seg = (N + AZ - 1) / AZ;
    int st = z * seg;
    int en = st + seg; if (en > N) en = N;

    float fklo = (float)klo;
    u64p vc[AE], vp[AE], t2p[AE], nt2p[AE], wp[AE];
#pragma unroll
    for (int e = 0; e < AE; e++) {
        int n = st + tid + e * ABLK;
        bool ok = (n < en);
        float a  = ok ? arow[n] : 0.f;
        float ww = ok ? w[n]    : 0.f;
        float us, uc;
        __sincosf(TWO_PI_F * a, &us, &uc);
        float t = fklo * a;
        float er = fmaf(fklo, a, -t);
        float f = (t - rintf(t)) + er;
        float zs, zc;
        __sincosf(TWO_PI_F * f, &zs, &zc);
        float zmc = fmaf(zc, uc,  zs * us);   // z_{klo-1} = z_klo * conj(u)
        float zms = fmaf(zs, uc, -zc * us);
        vc[e] = pk2(zc, zs);
        vp[e] = pk2(-zmc, -zms);
        t2p[e]  = pk2( 2.f * uc,  2.f * uc);
        nt2p[e] = pk2(-2.f * uc, -2.f * uc);
        wp[e] = pk2(ww, ww);
    }

    for (int c = 0; c < nchunk; c++) {
        int k0 = klo + c * ACH;
        u64p accv[ACH];
#pragma unroll
        for (int j = 0; j < ACH; j++) accv[j] = 0ull;

#pragma unroll
        for (int j = 0; j < ACH; j++) {
#pragma unroll
            for (int e = 0; e < AE; e++) {
                accv[j] = fma2(wp[e], vc[e], accv[j]);
                u64p vn = fma2((j & 1) ? nt2p[e] : t2p[e], vc[e], vp[e]);
                vp[e] = vc[e]; vc[e] = vn;
            }
        }

        // unpack: a[2j]=C_j, a[2j+1]=S_j
        float a[2 * ACH];
#pragma unroll
        for (int j = 0; j < ACH; j++) upk2(accv[j], a[2 * j], a[2 * j + 1]);

        // recursive-halving reduce-scatter: lane l ends owning index l
#pragma unroll
        for (int B = 16; B >= 1; B >>= 1) {
            bool bit = (lane & B) != 0;
#pragma unroll
            for (int i = 0; i < B; i++) {
                float snd = bit ? a[i] : a[i + B];
                float kp  = bit ? a[i + B] : a[i];
                a[i] = kp + __shfl_xor_sync(0xffffffffu, snd, B);
            }
        }

        int j = lane >> 1;
        int k = k0 + j;
        float sg = ((j & 2) == 0) ? 1.f : -1.f;   // sigma_j
        if (k <= 511) {
            float fkt = g_kft2[k];
            if (fkt != 0.f)
                atomicAdd(reinterpret_cast<float*>(g_CS + (size_t)p * KPAD + (k - 1)) + (lane & 1),
                          a[0] * (sg * fkt));
        }
    }
}

// ---------- forward helpers ----------
__device__ __forceinline__ void clenshaw_step(u64p& b1, u64p& b2, u64p t2, u64p negv, u64p coef) {
    u64p t = fma2(t2, b1, coef);
    u64p n = fma2(negv, b2, t);
    b2 = b1; b1 = n;
}
__device__ __forceinline__ float clenshaw_fin(u64p b1, u64p b2, float fk0,
                                              float bv, float cu, float su) {
    float t = fk0 * bv;
    float e = fmaf(fk0, bv, -t);
    float f = (t - rintf(t)) + e;
    float sK, cK;
    __sincosf(TWO_PI_F * f, &sK, &cK);
    float cKm = fmaf(cK, cu,  sK * su);
    float sKm = fmaf(sK, cu, -cK * su);
    float b1l, b1h, b2l, b2h;
    upk2(b1, b1l, b1h); upk2(b2, b2l, b2h);
    return fmaf(b1l, cK, -b2l * cKm) + fmaf(b1h, sK, -b2h * sKm);
}

// ---------- forward: split-range packed Clenshaw (2 halves x 2 slices = 4 chains) ----------
__global__ void __launch_bounds__(256) forward_kernel(float* __restrict__ out,
                                                      int M, int P) {
    int m = blockIdx.x * blockDim.x + threadIdx.x;
    if (m >= M) return;
    int hmax = g_hmax;
    if (hmax < 1) return;
    int kmin = g_kmin; if (kmin < 1) kmin = 1;
    int KE  = ((hmax + 1) >> 1) << 1;
    int jlo = ((kmin - 1) >> 1) << 1;
    int T = (KE - jlo) >> 1;        // coefficient pairs
    int L = (T + 1) >> 1;           // iters per half (upper padded into zero slots)
    int idx0 = jlo >> 1;            // base pair index
    float fklo = (float)(jlo + 1);
    float fkhi = (float)(jlo + 2 * L + 1);
    const u64p negv = pk2(-1.f, -1.f);

    int p0 = blockIdx.y * PG;
    float total = 0.f;

    if (p0 + 1 < P) {
        float ba = g_B[(size_t)p0 * M + m];
        float bb = g_B[(size_t)(p0 + 1) * M + m];
        float sa, ca, sb, cb;
        __sincosf(TWO_PI_F * ba, &sa, &ca);
        __sincosf(TWO_PI_F * bb, &sb, &cb);
        u64p t2a = pk2(2.f * ca, 2.f * ca);
        u64p t2b = pk2(2.f * cb, 2.f * cb);
        u64p a1 = 0ull, a2 = 0ull, h1 = 0ull, h2 = 0ull;
        u64p b1 = 0ull, b2 = 0ull, g1 = 0ull, g2 = 0ull;
        const ulonglong2* CA = reinterpret_cast<const ulonglong2*>(g_CS + (size_t)p0 * KPAD);
        const ulonglong2* CB = reinterpret_cast<const ulonglong2*>(g_CS + (size_t)(p0 + 1) * KPAD);
#pragma unroll 2
        for (int i = L - 1; i >= 0; i--) {
            ulonglong2 fa  = __ldg(CA + idx0 + i);
            ulonglong2 fah = __ldg(CA + idx0 + L + i);
            ulonglong2 fb  = __ldg(CB + idx0 + i);
            ulonglong2 fbh = __ldg(CB + idx0 + L + i);
            clenshaw_step(a1, a2, t2a, negv, fa.y);
            clenshaw_step(h1, h2, t2a, negv, fah.y);
            clenshaw_step(b1, b2, t2b, negv, fb.y);
            clenshaw_step(g1, g2, t2b, negv, fbh.y);
            clenshaw_step(a1, a2, t2a, negv, fa.x);
            clenshaw_step(h1, h2, t2a, negv, fah.x);
            clenshaw_step(b1, b2, t2b, negv, fb.x);
            clenshaw_step(g1, g2, t2b, negv, fbh.x);
        }
        total += clenshaw_fin(a1, a2, fklo, ba, ca, sa);
        total += clenshaw_fin(h1, h2, fkhi, ba, ca, sa);
        total += clenshaw_fin(b1, b2, fklo, bb, cb, sb);
        total += clenshaw_fin(g1, g2, fkhi, bb, cb, sb);
    } else if (p0 < P) {   // odd-P tail
        float ba = g_B[(size_t)p0 * M + m];
        float sa, ca;
        __sincosf(TWO_PI_F * ba, &sa, &ca);
        u64p t2a = pk2(2.f * ca, 2.f * ca);
        u64p a1 = 0ull, a2 = 0ull, h1 = 0ull, h2 = 0ull;
        const ulonglong2* CA = reinterpret_cast<const ulonglong2*>(g_CS + (size_t)p0 * KPAD);
#pragma unroll 2
        for (int i = L - 1; i >= 0; i--) {
            ulonglong2 fa  = __ldg(CA + idx0 + i);
            ulonglong2 fah = __ldg(CA + idx0 + L + i);
            clenshaw_step(a1, a2, t2a, negv, fa.y);
            clenshaw_step(h1, h2, t2a, negv, fah.y);
            clenshaw_step(a1, a2, t2a, negv, fa.x);
            clenshaw_step(h1, h2, t2a, negv, fah.x);
        }
        total += clenshaw_fin(a1, a2, fklo, ba, ca, sa);
        total += clenshaw_fin(h1, h2, fkhi, ba, ca, sa);
    }
    atomicAdd(out + m, total);
}

extern "C" void kernel_launch(void* const* d_in, const int* in_sizes, int n_in,
                              void* d_out, int out_size) {
    const float* x     = (const float*)d_in[0];
    const float* y     = (const float*)d_in[1];
    const float* w     = (const float*)d_in[2];
    const float* scale = (const float*)d_in[3];
    const float* xis   = (const float*)d_in[4];
    float* out = (float*)d_out;

    int N = in_sizes[2];
    int d = in_sizes[0] / N;
    int M = out_size;
    int P = in_sizes[4] / d;

    int nb = (N + M + 255) / 256;
    if (nb > 256) nb = 256;
    norm_init_kernel<<<nb, 256>>>(x, y, out, N, M, d);
    kft_kernel<<<1, 512>>>(scale, P, (float)d, nb);
    int nmax = (N > M) ? N : M;
    dim3 pgrid((nmax + PROJ_PTS - 1) / PROJ_PTS, 2);
    proj4_kernel<<<pgrid, 256>>>(x, y, xis, N, M, P);
    adjoint_kernel<<<dim3(P, AZ), ABLK>>>(w, N);
    int ngroups = (P + PG - 1) / PG;
    forward_kernel<<<dim3((M + 255) / 256, ngroups), 256>>>(out, M, P);
}

// round 10
// speedup vs baseline: 1.3578x; 1.1150x over previous
#include <cuda_runtime.h>
#include <math.h>

#define TWO_PI_F  6.28318530717958647692f
#define TWO_PI2_F 19.739208802178716f   /* 2*pi^2 */

#define NMAX 8192
#define PMAX 64
#define KPAD 520
#define ACH 16             /* k per adjoint chunk (multiple of 4!) */
#define AZ 16              /* adjoint N-splits */
#define AE 8               /* elements per adjoint thread */
#define ABLK 64            /* adjoint block size */
#define PROJ_PTS 128
#define PG 2               /* slices per forward block */

typedef unsigned long long u64p;

// ---------- packed f32x2 helpers ----------
__device__ __forceinline__ u64p pk2(float lo, float hi) {
    u64p r; asm("mov.b64 %0, {%1, %2};" : "=l"(r) : "f"(lo), "f"(hi)); return r;
}
__device__ __forceinline__ void upk2(u64p v, float& lo, float& hi) {
    asm("mov.b64 {%0, %1}, %2;" : "=f"(lo), "=f"(hi) : "l"(v));
}
__device__ __forceinline__ u64p fma2(u64p a, u64p b, u64p c) {
    u64p d; asm("fma.rn.f32x2 %0, %1, %2, %3;" : "=l"(d) : "l"(a), "l"(b), "l"(c)); return d;
}

// ---------- device scratch ----------
__device__ float  g_A[PMAX * NMAX];    // sf * <x_n, xi_p>, [p][n]
__device__ float  g_B[PMAX * NMAX];    // sf * <y_m, xi_p>, [p][m]
__device__ float2 g_CS[PMAX * KPAD];   // (C*kft2, S*kft2), slot j = k-1
__device__ float  g_kft2[KPAD];        // 2*kft(h)/P, thresholded
__device__ unsigned int g_norm2max_bits;   // reset by last block each call
__device__ unsigned int g_ctr;             // reset by last block each call
__device__ int    g_hmax;
__device__ int    g_kmin;
__device__ float  g_sf;

// ---------- fused: zero buffers + row-norm max + kft (last-block pattern) ----------
__global__ void __launch_bounds__(256) norm_kft_kernel(
        const float* __restrict__ x, const float* __restrict__ y,
        const float* __restrict__ scale, float* __restrict__ out,
        int N, int M, int d, float dd, int P) {
    __shared__ float wmax[8];
    __shared__ float sred[256];
    __shared__ int s_flag, s_hmax, s_kmin;
    int tid = threadIdx.x;
    int i = blockIdx.x * 256 + tid;
    int stride = gridDim.x * 256;

    // zero g_CS and out
    float2 z2 = make_float2(0.f, 0.f);
    for (int j = i; j < PMAX * KPAD; j += stride) g_CS[j] = z2;
    for (int j = i; j < M; j += stride) out[j] = 0.f;

    // row norm^2 max
    float v = 0.f;
    int T = N + M;
    if (i < T) {
        const float* row = (i < N) ? (x + (size_t)i * d) : (y + (size_t)(i - N) * d);
        float s = 0.f;
        for (int j = 0; j < d; j += 4) {
            float4 q = *reinterpret_cast<const float4*>(row + j);
            s = fmaf(q.x, q.x, s); s = fmaf(q.y, q.y, s);
            s = fmaf(q.z, q.z, s); s = fmaf(q.w, q.w, s);
        }
        v = s;
    }
#pragma unroll
    for (int off = 16; off > 0; off >>= 1)
        v = fmaxf(v, __shfl_xor_sync(0xffffffffu, v, off));
    if ((tid & 31) == 0) wmax[tid >> 5] = v;
    __syncthreads();
    if (tid == 0) {
        float m = wmax[0];
#pragma unroll
        for (int wq = 1; wq < 8; wq++) m = fmaxf(m, wmax[wq]);
        if (m > 0.f) atomicMax(&g_norm2max_bits, __float_as_uint(m));
        __threadfence();
        unsigned int prev = atomicAdd(&g_ctr, 1u);
        s_flag = (prev == gridDim.x - 1) ? 1 : 0;
    }
    __syncthreads();
    if (!s_flag) return;

    // ---- last block: compute kft, thresholds, sf ----
    __threadfence();
    unsigned int nb_bits = atomicAdd(&g_norm2max_bits, 0u);   // atomic read
    float nm = sqrtf(__uint_as_float(nb_bits));
    float sf = 0.3f / nm;
    float sr = scale[0] * sf;
    float s2 = sr * sr;
    float base = 0.5f * dd * __logf(TWO_PI2_F * s2) - lgammaf(0.5f * dd);

    int h1 = tid + 1;           // 1..256
    int h2 = tid + 257;         // 257..512
    float k1 = 0.f, k2 = 0.f;
    {
        float hp = (float)h1;
        float lv = base + (dd - 1.f) * __logf(hp) - TWO_PI2_F * s2 * hp * hp;
        k1 = __expf(lv);
    }
    if (h2 <= 511) {
        float hp = (float)h2;
        float lv = base + (dd - 1.f) * __logf(hp) - TWO_PI2_F * s2 * hp * hp;
        k2 = __expf(lv);
    }
    sred[tid] = fmaxf(k1, k2);
    if (tid == 0) { s_hmax = 0; s_kmin = 0x7fffffff; }
    __syncthreads();
    for (int s = 128; s > 0; s >>= 1) {
        if (tid < s) sred[tid] = fmaxf(sred[tid], sred[tid + s]);
        __syncthreads();
    }
    float maxv = sred[0];
    float thr = maxv * 1e-7f;
    float fscale = 2.f / (float)P;

    bool keep1 = (maxv > 0.f) && (k1 > thr);
    g_kft2[h1] = keep1 ? k1 * fscale : 0.f;
    if (keep1) { atomicMax(&s_hmax, h1); atomicMin(&s_kmin, h1); }
    if (h2 <= 511) {
        bool keep2 = (maxv > 0.f) && (k2 > thr);
        g_kft2[h2] = keep2 ? k2 * fscale : 0.f;
        if (keep2) { atomicMax(&s_hmax, h2); atomicMin(&s_kmin, h2); }
    }
    __syncthreads();
    if (tid == 0) {
        g_kft2[0] = 0.f;
        g_hmax = s_hmax;
        g_kmin = s_kmin;
        g_sf = sf;
        g_ctr = 0u;             // reset for next graph replay
        g_norm2max_bits = 0u;
    }
}

// ---------- proj5: smem-staged, P split in halves across blockIdx.z ----------
__global__ void __launch_bounds__(256) proj5_kernel(const float* __restrict__ xpts,
                                                    const float* __restrict__ ypts,
                                                    const float* __restrict__ xis,
                                                    int N, int M, int P) {
    __shared__ float xi_t[64 * 34];          // [dim][p_local 0..31], stride 34
    __shared__ float pts_s[PROJ_PTS * 68];   // [row][dim], stride 68
    int tid = threadIdx.x;
    int which = blockIdx.y;
    int pbase = blockIdx.z * 32;
    const float* pts = which ? ypts : xpts;
    int npts = which ? M : N;
    int base = blockIdx.x * PROJ_PTS;

    // stage 32 xi rows, transposed
    for (int idx = tid; idx < 32 * 64; idx += 256) {
        int pl = idx >> 6, dc = idx & 63;
        int pg = pbase + pl;
        xi_t[dc * 34 + pl] = (pg < P) ? xis[(size_t)pg * 64 + dc] : 0.f;
    }
    // stage 128 point rows (coalesced)
    for (int idx = tid; idx < PROJ_PTS * 16; idx += 256) {
        int r = idx >> 4, j4 = idx & 15;
        int n = base + r;
        float4 v = make_float4(0.f, 0.f, 0.f, 0.f);
        if (n < npts) v = *reinterpret_cast<const float4*>(pts + (size_t)n * 64 + j4 * 4);
        *reinterpret_cast<float4*>(pts_s + r * 68 + j4 * 4) = v;
    }
    __syncthreads();

    int slot = tid & 63;
    int g = tid >> 6;                 // 4 groups of 8 ps
    const float4* r0 = reinterpret_cast<const float4*>(pts_s + slot * 68);
    const float4* r1 = reinterpret_cast<const float4*>(pts_s + (slot + 64) * 68);

    u64p acc0[4], acc1[4];
#pragma unroll
    for (int q = 0; q < 4; q++) { acc0[q] = 0ull; acc1[q] = 0ull; }

#pragma unroll
    for (int j4 = 0; j4 < 16; j4++) {
        float4 v0 = r0[j4];
        float4 v1 = r1[j4];
#pragma unroll
        for (int s = 0; s < 4; s++) {
            float f0 = (s == 0) ? v0.x : (s == 1) ? v0.y : (s == 2) ? v0.z : v0.w;
            float f1 = (s == 0) ? v1.x : (s == 1) ? v1.y : (s == 2) ? v1.z : v1.w;
            u64p vv0 = pk2(f0, f0);
            u64p vv1 = pk2(f1, f1);
            const float* xb = xi_t + (j4 * 4 + s) * 34 + g * 8;
#pragma unroll
            for (int q = 0; q < 4; q++) {
                u64p xq = *reinterpret_cast<const u64p*>(xb + 2 * q);
                acc0[q] = fma2(vv0, xq, acc0[q]);
                acc1[q] = fma2(vv1, xq, acc1[q]);
            }
        }
    }

    float sf = g_sf;
    float* dst = which ? g_B : g_A;
    int n0 = base + slot, n1 = n0 + 64;
#pragma unroll
    for (int q = 0; q < 4; q++) {
        float a, b, c, dq;
        upk2(acc0[q], a, b);
        upk2(acc1[q], c, dq);
        int p0 = pbase + g * 8 + 2 * q;
        if (p0 < P) {
            if (n0 < npts) dst[(size_t)p0 * npts + n0] = a * sf;
            if (n1 < npts) dst[(size_t)p0 * npts + n1] = c * sf;
        }
        if (p0 + 1 < P) {
            if (n0 < npts) dst[(size_t)(p0 + 1) * npts + n0] = b * sf;
            if (n1 < npts) dst[(size_t)(p0 + 1) * npts + n1] = dq * sf;
        }
    }
}

// ---------- adjoint: chunk-carried Chebyshev + warp reduce-scatter, AE=8, block=64 ----------
__global__ void __launch_bounds__(ABLK) adjoint_kernel(const float* __restrict__ w, int N) {
    int p = blockIdx.x;
    int z = blockIdx.y;
    int hmax = g_hmax;
    if (hmax < 1) return;
    int klo = g_kmin; if (klo < 1) klo = 1;
    int nchunk = (hmax - klo + ACH) / ACH;

    int tid = threadIdx.x;
    int lane = tid & 31;
    const float* arow = g_A + (size_t)p * N;
    int seg = (N + AZ - 1) / AZ;
    int st = z * seg;
    int en = st + seg; if (en > N) en = N;

    float fklo = (float)klo;
    u64p vc[AE], vp[AE], t2p[AE], nt2p[AE], wp[AE];
#pragma unroll
    for (int e = 0; e < AE; e++) {
        int n = st + tid + e * ABLK;
        bool ok = (n < en);
        float a  = ok ? arow[n] : 0.f;
        float ww = ok ? w[n]    : 0.f;
        float us, uc;
        __sincosf(TWO_PI_F * a, &us, &uc);
        float t = fklo * a;
        float er = fmaf(fklo, a, -t);
        float f = (t - rintf(t)) + er;
        float zs, zc;
        __sincosf(TWO_PI_F * f, &zs, &zc);
        float zmc = fmaf(zc, uc,  zs * us);   // z_{klo-1} = z_klo * conj(u)
        float zms = fmaf(zs, uc, -zc * us);
        vc[e] = pk2(zc, zs);
        vp[e] = pk2(-zmc, -zms);
        t2p[e]  = pk2( 2.f * uc,  2.f * uc);
        nt2p[e] = pk2(-2.f * uc, -2.f * uc);
        wp[e] = pk2(ww, ww);
    }

    for (int c = 0; c < nchunk; c++) {
        int k0 = klo + c * ACH;
        u64p accv[ACH];
#pragma unroll
        for (int j = 0; j < ACH; j++) accv[j] = 0ull;

#pragma unroll
        for (int j = 0; j < ACH; j++) {
#pragma unroll
            for (int e = 0; e < AE; e++) {
                accv[j] = fma2(wp[e], vc[e], accv[j]);
                u64p vn = fma2((j & 1) ? nt2p[e] : t2p[e], vc[e], vp[e]);
                vp[e] = vc[e]; vc[e] = vn;
            }
        }

        float a[2 * ACH];
#pragma unroll
        for (int j = 0; j < ACH; j++) upk2(accv[j], a[2 * j], a[2 * j + 1]);

        // recursive-halving reduce-scatter: lane l ends owning index l
#pragma unroll
        for (int B = 16; B >= 1; B >>= 1) {
            bool bit = (lane & B) != 0;
#pragma unroll
            for (int i = 0; i < B; i++) {
                float snd = bit ? a[i] : a[i + B];
                float kp  = bit ? a[i + B] : a[i];
                a[i] = kp + __shfl_xor_sync(0xffffffffu, snd, B);
            }
        }

        int j = lane >> 1;
        int k = k0 + j;
        float sg = ((j & 2) == 0) ? 1.f : -1.f;   // sigma_j
        if (k <= 511) {
            float fkt = g_kft2[k];
            if (fkt != 0.f)
                atomicAdd(reinterpret_cast<float*>(g_CS + (size_t)p * KPAD + (k - 1)) + (lane & 1),
                          a[0] * (sg * fkt));
        }
    }
}

// ---------- forward helpers ----------
__device__ __forceinline__ void clenshaw_step(u64p& b1, u64p& b2, u64p t2, u64p negv, u64p coef) {
    u64p t = fma2(t2, b1, coef);
    u64p n = fma2(negv, b2, t);
    b2 = b1; b1 = n;
}
__device__ __forceinline__ float clenshaw_fin(u64p b1, u64p b2, float fk0,
                                              float bv, float cu, float su) {
    float t = fk0 * bv;
    float e = fmaf(fk0, bv, -t);
    float f = (t - rintf(t)) + e;
    float sK, cK;
    __sincosf(TWO_PI_F * f, &sK, &cK);
    float cKm = fmaf(cK, cu,  sK * su);
    float sKm = fmaf(sK, cu, -cK * su);
    float b1l, b1h, b2l, b2h;
    upk2(b1, b1l, b1h); upk2(b2, b2l, b2h);
    return fmaf(b1l, cK, -b2l * cKm) + fmaf(b1h, sK, -b2h * sKm);
}

// ---------- forward: split-range packed Clenshaw (2 halves x 2 slices = 4 chains) ----------
__global__ void __launch_bounds__(256) forward_kernel(float* __restrict__ out,
                                                      int M, int P) {
    int m = blockIdx.x * blockDim.x + threadIdx.x;
    if (m >= M) return;
    int hmax = g_hmax;
    if (hmax < 1) return;
    int kmin = g_kmin; if (kmin < 1) kmin = 1;
    int KE  = ((hmax + 1) >> 1) << 1;
    int jlo = ((kmin - 1) >> 1) << 1;
    int T = (KE - jlo) >> 1;        // coefficient pairs
    int L = (T + 1) >> 1;           // iters per half (upper padded into zero slots)
    int idx0 = jlo >> 1;            // base pair index
    float fklo = (float)(jlo + 1);
    float fkhi = (float)(jlo + 2 * L + 1);
    const u64p negv = pk2(-1.f, -1.f);

    int p0 = blockIdx.y * PG;
    float total = 0.f;

    if (p0 + 1 < P) {
        float ba = g_B[(size_t)p0 * M + m];
        float bb = g_B[(size_t)(p0 + 1) * M + m];
        float sa, ca, sb, cb;
        __sincosf(TWO_PI_F * ba, &sa, &ca);
        __sincosf(TWO_PI_F * bb, &sb, &cb);
        u64p t2a = pk2(2.f * ca, 2.f * ca);
        u64p t2b = pk2(2.f * cb, 2.f * cb);
        u64p a1 = 0ull, a2 = 0ull, h1 = 0ull, h2 = 0ull;
        u64p b1 = 0ull, b2 = 0ull, g1 = 0ull, g2 = 0ull;
        const ulonglong2* CA = reinterpret_cast<const ulonglong2*>(g_CS + (size_t)p0 * KPAD);
        const ulonglong2* CB = reinterpret_cast<const ulonglong2*>(g_CS + (size_t)(p0 + 1) * KPAD);
#pragma unroll 2
        for (int i = L - 1; i >= 0; i--) {
            ulonglong2 fa  = __ldg(CA + idx0 + i);
            ulonglong2 fah = __ldg(CA + idx0 + L + i);
            ulonglong2 fb  = __ldg(CB + idx0 + i);
            ulonglong2 fbh = __ldg(CB + idx0 + L + i);
            clenshaw_step(a1, a2, t2a, negv, fa.y);
            clenshaw_step(h1, h2, t2a, negv, fah.y);
            clenshaw_step(b1, b2, t2b, negv, fb.y);
            clenshaw_step(g1, g2, t2b, negv, fbh.y);
            clenshaw_step(a1, a2, t2a, negv, fa.x);
            clenshaw_step(h1, h2, t2a, negv, fah.x);
            clenshaw_step(b1, b2, t2b, negv, fb.x);
            clenshaw_step(g1, g2, t2b, negv, fbh.x);
        }
        total += clenshaw_fin(a1, a2, fklo, ba, ca, sa);
        total += clenshaw_fin(h1, h2, fkhi, ba, ca, sa);
        total += clenshaw_fin(b1, b2, fklo, bb, cb, sb);
        total += clenshaw_fin(g1, g2, fkhi, bb, cb, sb);
    } else if (p0 < P) {   // odd-P tail
        float ba = g_B[(size_t)p0 * M + m];
        float sa, ca;
        __sincosf(TWO_PI_F * ba, &sa, &ca);
        u64p t2a = pk2(2.f * ca, 2.f * ca);
        u64p a1 = 0ull, a2 = 0ull, h1 = 0ull, h2 = 0ull;
        const ulonglong2* CA = reinterpret_cast<const ulonglong2*>(g_CS + (size_t)p0 * KPAD);
#pragma unroll 2
        for (int i = L - 1; i >= 0; i--) {
            ulonglong2 fa  = __ldg(CA + idx0 + i);
            ulonglong2 fah = __ldg(CA + idx0 + L + i);
            clenshaw_step(a1, a2, t2a, negv, fa.y);
            clenshaw_step(h1, h2, t2a, negv, fah.y);
            clenshaw_step(a1, a2, t2a, negv, fa.x);
            clenshaw_step(h1, h2, t2a, negv, fah.x);
        }
        total += clenshaw_fin(a1, a2, fklo, ba, ca, sa);
        total += clenshaw_fin(h1, h2, fkhi, ba, ca, sa);
    }
    atomicAdd(out + m, total);
}

extern "C" void kernel_launch(void* const* d_in, const int* in_sizes, int n_in,
                              void* d_out, int out_size) {
    const float* x     = (const float*)d_in[0];
    const float* y     = (const float*)d_in[1];
    const float* w     = (const float*)d_in[2];
    const float* scale = (const float*)d_in[3];
    const float* xis   = (const float*)d_in[4];
    float* out = (float*)d_out;

    int N = in_sizes[2];
    int d = in_sizes[0] / N;
    int M = out_size;
    int P = in_sizes[4] / d;

    int nb = (N + M + 255) / 256;
    norm_kft_kernel<<<nb, 256>>>(x, y, scale, out, N, M, d, (float)d, P);
    int nmax = (N > M) ? N : M;
    dim3 pgrid((nmax + PROJ_PTS - 1) / PROJ_PTS, 2, 2);
    proj5_kernel<<<pgrid, 256>>>(x, y, xis, N, M, P);
    adjoint_kernel<<<dim3(P, AZ), ABLK>>>(w, N);
    int ngroups = (P + PG - 1) / PG;
    forward_kernel<<<dim3((M + 255) / 256, ngroups), 256>>>(out, M, P);
}

// round 11
// speedup vs baseline: 1.4317x; 1.0544x over previous
#include <cuda_runtime.h>
#include <math.h>

#define TWO_PI_F  6.28318530717958647692f
#define TWO_PI2_F 19.739208802178716f   /* 2*pi^2 */

#define NMAX 8192
#define PMAX 64
#define KPAD 520
#define ACH 16             /* k per adjoint chunk (multiple of 4!) */
#define AZ 16              /* adjoint N-splits */
#define AE 8               /* elements per adjoint thread */
#define ABLK 64            /* adjoint block size */
#define PROJ_PTS 128
#define PG 2               /* slices per forward block */
#define FBLK 128           /* forward block size */

typedef unsigned long long u64p;

// ---------- packed f32x2 helpers ----------
__device__ __forceinline__ u64p pk2(float lo, float hi) {
    u64p r; asm("mov.b64 %0, {%1, %2};" : "=l"(r) : "f"(lo), "f"(hi)); return r;
}
__device__ __forceinline__ void upk2(u64p v, float& lo, float& hi) {
    asm("mov.b64 {%0, %1}, %2;" : "=f"(lo), "=f"(hi) : "l"(v));
}
__device__ __forceinline__ u64p fma2(u64p a, u64p b, u64p c) {
    u64p d; asm("fma.rn.f32x2 %0, %1, %2, %3;" : "=l"(d) : "l"(a), "l"(b), "l"(c)); return d;
}

// ---------- device scratch ----------
__device__ float  g_A[PMAX * NMAX];    // sf * <x_n, xi_p>, [p][n]
__device__ float  g_B[PMAX * NMAX];    // sf * <y_m, xi_p>, [p][m]
__device__ float2 g_CS[PMAX * KPAD];   // (C*kft2, S*kft2), slot j = k-1
__device__ float  g_kft2[KPAD];        // 2*kft(h)/P, thresholded
__device__ unsigned int g_norm2max_bits;   // reset by last block each call
__device__ unsigned int g_ctr;             // reset by last block each call
__device__ int    g_hmax;
__device__ int    g_kmin;
__device__ float  g_sf;

// ---------- fused: zero buffers + row-norm max + kft (last-block pattern) ----------
__global__ void __launch_bounds__(256) norm_kft_kernel(
        const float* __restrict__ x, const float* __restrict__ y,
        const float* __restrict__ scale, float* __restrict__ out,
        int N, int M, int d, float dd, int P) {
    __shared__ float wmax[8];
    __shared__ float sred[256];
    __shared__ int s_flag, s_hmax, s_kmin;
    int tid = threadIdx.x;
    int i = blockIdx.x * 256 + tid;
    int stride = gridDim.x * 256;

    float2 z2 = make_float2(0.f, 0.f);
    for (int j = i; j < PMAX * KPAD; j += stride) g_CS[j] = z2;
    for (int j = i; j < M; j += stride) out[j] = 0.f;

    float v = 0.f;
    int T = N + M;
    if (i < T) {
        const float* row = (i < N) ? (x + (size_t)i * d) : (y + (size_t)(i - N) * d);
        float s = 0.f;
        for (int j = 0; j < d; j += 4) {
            float4 q = *reinterpret_cast<const float4*>(row + j);
            s = fmaf(q.x, q.x, s); s = fmaf(q.y, q.y, s);
            s = fmaf(q.z, q.z, s); s = fmaf(q.w, q.w, s);
        }
        v = s;
    }
#pragma unroll
    for (int off = 16; off > 0; off >>= 1)
        v = fmaxf(v, __shfl_xor_sync(0xffffffffu, v, off));
    if ((tid & 31) == 0) wmax[tid >> 5] = v;
    __syncthreads();
    if (tid == 0) {
        float m = wmax[0];
#pragma unroll
        for (int wq = 1; wq < 8; wq++) m = fmaxf(m, wmax[wq]);
        if (m > 0.f) atomicMax(&g_norm2max_bits, __float_as_uint(m));
        __threadfence();
        unsigned int prev = atomicAdd(&g_ctr, 1u);
        s_flag = (prev == gridDim.x - 1) ? 1 : 0;
    }
    __syncthreads();
    if (!s_flag) return;

    __threadfence();
    unsigned int nb_bits = atomicAdd(&g_norm2max_bits, 0u);
    float nm = sqrtf(__uint_as_float(nb_bits));
    float sf = 0.3f / nm;
    float sr = scale[0] * sf;
    float s2 = sr * sr;
    float base = 0.5f * dd * __logf(TWO_PI2_F * s2) - lgammaf(0.5f * dd);

    int h1 = tid + 1;
    int h2 = tid + 257;
    float k1 = 0.f, k2 = 0.f;
    {
        float hp = (float)h1;
        float lv = base + (dd - 1.f) * __logf(hp) - TWO_PI2_F * s2 * hp * hp;
        k1 = __expf(lv);
    }
    if (h2 <= 511) {
        float hp = (float)h2;
        float lv = base + (dd - 1.f) * __logf(hp) - TWO_PI2_F * s2 * hp * hp;
        k2 = __expf(lv);
    }
    sred[tid] = fmaxf(k1, k2);
    if (tid == 0) { s_hmax = 0; s_kmin = 0x7fffffff; }
    __syncthreads();
    for (int s = 128; s > 0; s >>= 1) {
        if (tid < s) sred[tid] = fmaxf(sred[tid], sred[tid + s]);
        __syncthreads();
    }
    float maxv = sred[0];
    float thr = maxv * 1e-7f;
    float fscale = 2.f / (float)P;

    bool keep1 = (maxv > 0.f) && (k1 > thr);
    g_kft2[h1] = keep1 ? k1 * fscale : 0.f;
    if (keep1) { atomicMax(&s_hmax, h1); atomicMin(&s_kmin, h1); }
    if (h2 <= 511) {
        bool keep2 = (maxv > 0.f) && (k2 > thr);
        g_kft2[h2] = keep2 ? k2 * fscale : 0.f;
        if (keep2) { atomicMax(&s_hmax, h2); atomicMin(&s_kmin, h2); }
    }
    __syncthreads();
    if (tid == 0) {
        g_kft2[0] = 0.f;
        g_hmax = s_hmax;
        g_kmin = s_kmin;
        g_sf = sf;
        g_ctr = 0u;
        g_norm2max_bits = 0u;
    }
}

// ---------- proj5: smem-staged, P split in halves across blockIdx.z ----------
__global__ void __launch_bounds__(256) proj5_kernel(const float* __restrict__ xpts,
                                                    const float* __restrict__ ypts,
                                                    const float* __restrict__ xis,
                                                    int N, int M, int P) {
    __shared__ float xi_t[64 * 34];
    __shared__ float pts_s[PROJ_PTS * 68];
    int tid = threadIdx.x;
    int which = blockIdx.y;
    int pbase = blockIdx.z * 32;
    const float* pts = which ? ypts : xpts;
    int npts = which ? M : N;
    int base = blockIdx.x * PROJ_PTS;

    for (int idx = tid; idx < 32 * 64; idx += 256) {
        int pl = idx >> 6, dc = idx & 63;
        int pg = pbase + pl;
        xi_t[dc * 34 + pl] = (pg < P) ? xis[(size_t)pg * 64 + dc] : 0.f;
    }
    for (int idx = tid; idx < PROJ_PTS * 16; idx += 256) {
        int r = idx >> 4, j4 = idx & 15;
        int n = base + r;
        float4 v = make_float4(0.f, 0.f, 0.f, 0.f);
        if (n < npts) v = *reinterpret_cast<const float4*>(pts + (size_t)n * 64 + j4 * 4);
        *reinterpret_cast<float4*>(pts_s + r * 68 + j4 * 4) = v;
    }
    __syncthreads();

    int slot = tid & 63;
    int g = tid >> 6;
    const float4* r0 = reinterpret_cast<const float4*>(pts_s + slot * 68);
    const float4* r1 = reinterpret_cast<const float4*>(pts_s + (slot + 64) * 68);

    u64p acc0[4], acc1[4];
#pragma unroll
    for (int q = 0; q < 4; q++) { acc0[q] = 0ull; acc1[q] = 0ull; }

#pragma unroll
    for (int j4 = 0; j4 < 16; j4++) {
        float4 v0 = r0[j4];
        float4 v1 = r1[j4];
#pragma unroll
        for (int s = 0; s < 4; s++) {
            float f0 = (s == 0) ? v0.x : (s == 1) ? v0.y : (s == 2) ? v0.z : v0.w;
            float f1 = (s == 0) ? v1.x : (s == 1) ? v1.y : (s == 2) ? v1.z : v1.w;
            u64p vv0 = pk2(f0, f0);
            u64p vv1 = pk2(f1, f1);
            const float* xb = xi_t + (j4 * 4 + s) * 34 + g * 8;
#pragma unroll
            for (int q = 0; q < 4; q++) {
                u64p xq = *reinterpret_cast<const u64p*>(xb + 2 * q);
                acc0[q] = fma2(vv0, xq, acc0[q]);
                acc1[q] = fma2(vv1, xq, acc1[q]);
            }
        }
    }

    float sf = g_sf;
    float* dst = which ? g_B : g_A;
    int n0 = base + slot, n1 = n0 + 64;
#pragma unroll
    for (int q = 0; q < 4; q++) {
        float a, b, c, dq;
        upk2(acc0[q], a, b);
        upk2(acc1[q], c, dq);
        int p0 = pbase + g * 8 + 2 * q;
        if (p0 < P) {
            if (n0 < npts) dst[(size_t)p0 * npts + n0] = a * sf;
            if (n1 < npts) dst[(size_t)p0 * npts + n1] = c * sf;
        }
        if (p0 + 1 < P) {
            if (n0 < npts) dst[(size_t)(p0 + 1) * npts + n0] = b * sf;
            if (n1 < npts) dst[(size_t)(p0 + 1) * npts + n1] = dq * sf;
        }
    }
}

// ---------- adjoint: chunk-carried Chebyshev + warp reduce-scatter, AE=8, block=64 ----------
__global__ void __launch_bounds__(ABLK) adjoint_kernel(const float* __restrict__ w, int N) {
    int p = blockIdx.x;
    int z = blockIdx.y;
    int hmax = g_hmax;
    if (hmax < 1) return;
    int klo = g_kmin; if (klo < 1) klo = 1;
    int nchunk = (hmax - klo + ACH) / ACH;

    int tid = threadIdx.x;
    int lane = tid & 31;
    const float* arow = g_A + (size_t)p * N;
    int seg = (N + AZ - 1) / AZ;
    int st = z * seg;
    int en = st + seg; if (en > N) en = N;

    float fklo = (float)klo;
    u64p vc[AE], vp[AE], t2p[AE], nt2p[AE], wp[AE];
#pragma unroll
    for (int e = 0; e < AE; e++) {
        int n = st + tid + e * ABLK;
        bool ok = (n < en);
        float a  = ok ? arow[n] : 0.f;
        float ww = ok ? w[n]    : 0.f;
        float us, uc;
        __sincosf(TWO_PI_F * a, &us, &uc);
        float t = fklo * a;
        float er = fmaf(fklo, a, -t);
        float f = (t - rintf(t)) + er;
        float zs, zc;
        __sincosf(TWO_PI_F * f, &zs, &zc);
        float zmc = fmaf(zc, uc,  zs * us);
        float zms = fmaf(zs, uc, -zc * us);
        vc[e] = pk2(zc, zs);
        vp[e] = pk2(-zmc, -zms);
        t2p[e]  = pk2( 2.f * uc,  2.f * uc);
        nt2p[e] = pk2(-2.f * uc, -2.f * uc);
        wp[e] = pk2(ww, ww);
    }

    for (int c = 0; c < nchunk; c++) {
        int k0 = klo + c * ACH;
        u64p accv[ACH];
#pragma unroll
        for (int j = 0; j < ACH; j++) accv[j] = 0ull;

#pragma unroll
        for (int j = 0; j < ACH; j++) {
#pragma unroll
            for (int e = 0; e < AE; e++) {
                accv[j] = fma2(wp[e], vc[e], accv[j]);
                u64p vn = fma2((j & 1) ? nt2p[e] : t2p[e], vc[e], vp[e]);
                vp[e] = vc[e]; vc[e] = vn;
            }
        }

        float a[2 * ACH];
#pragma unroll
        for (int j = 0; j < ACH; j++) upk2(accv[j], a[2 * j], a[2 * j + 1]);

#pragma unroll
        for (int B = 16; B >= 1; B >>= 1) {
            bool bit = (lane & B) != 0;
#pragma unroll
            for (int i = 0; i < B; i++) {
                float snd = bit ? a[i] : a[i + B];
                float kp  = bit ? a[i + B] : a[i];
                a[i] = kp + __shfl_xor_sync(0xffffffffu, snd, B);
            }
        }

        int j = lane >> 1;
        int k = k0 + j;
        float sg = ((j & 2) == 0) ? 1.f : -1.f;
        if (k <= 511) {
            float fkt = g_kft2[k];
            if (fkt != 0.f)
                atomicAdd(reinterpret_cast<float*>(g_CS + (size_t)p * KPAD + (k - 1)) + (lane & 1),
                          a[0] * (sg * fkt));
        }
    }
}

// ---------- forward helpers ----------
__device__ __forceinline__ void clenshaw_step(u64p& b1, u64p& b2, u64p t2, u64p negv, u64p coef) {
    u64p t = fma2(t2, b1, coef);
    u64p n = fma2(negv, b2, t);
    b2 = b1; b1 = n;
}
__device__ __forceinline__ float clenshaw_fin(u64p b1, u64p b2, float fk0,
                                              float bv, float cu, float su) {
    float t = fk0 * bv;
    float e = fmaf(fk0, bv, -t);
    float f = (t - rintf(t)) + e;
    float sK, cK;
    __sincosf(TWO_PI_F * f, &sK, &cK);
    float cKm = fmaf(cK, cu,  sK * su);
    float sKm = fmaf(sK, cu, -cK * su);
    float b1l, b1h, b2l, b2h;
    upk2(b1, b1l, b1h); upk2(b2, b2l, b2h);
    return fmaf(b1l, cK, -b2l * cKm) + fmaf(b1h, sK, -b2h * sKm);
}

// ---------- forward: MV=2 split-range Clenshaw (2 m x 2 slices x 2 halves = 8 chains) ----------
// Coefficient LDGs amortize over two targets; 8 independent chains saturate issue.
__global__ void __launch_bounds__(FBLK) forward_kernel(float* __restrict__ out,
                                                       int M, int P) {
    int hmax = g_hmax;
    if (hmax < 1) return;
    int kmin = g_kmin; if (kmin < 1) kmin = 1;
    int KE  = ((hmax + 1) >> 1) << 1;
    int jlo = ((kmin - 1) >> 1) << 1;
    int T = (KE - jlo) >> 1;        // coefficient pairs
    int L = (T + 1) >> 1;           // iters per half (upper padded into zero slots)
    int idx0 = jlo >> 1;
    float fklo = (float)(jlo + 1);
    float fkhi = (float)(jlo + 2 * L + 1);
    const u64p negv = pk2(-1.f, -1.f);

    int Mh = (M + 1) >> 1;
    int i = blockIdx.x * FBLK + threadIdx.x;
    if (i >= Mh) return;
    int m0 = i, m1 = i + Mh;
    bool has1 = (m1 < M);
    int p0 = blockIdx.y * PG;

    if (p0 + 1 < P) {
        float ba0 = g_B[(size_t)p0 * M + m0];
        float bb0 = g_B[(size_t)(p0 + 1) * M + m0];
        float ba1 = has1 ? g_B[(size_t)p0 * M + m1] : 0.f;
        float bb1 = has1 ? g_B[(size_t)(p0 + 1) * M + m1] : 0.f;
        float sa0, ca0, sb0, cb0, sa1, ca1, sb1, cb1;
        __sincosf(TWO_PI_F * ba0, &sa0, &ca0);
        __sincosf(TWO_PI_F * bb0, &sb0, &cb0);
        __sincosf(TWO_PI_F * ba1, &sa1, &ca1);
        __sincosf(TWO_PI_F * bb1, &sb1, &cb1);
        u64p t2a0 = pk2(2.f * ca0, 2.f * ca0);
        u64p t2b0 = pk2(2.f * cb0, 2.f * cb0);
        u64p t2a1 = pk2(2.f * ca1, 2.f * ca1);
        u64p t2b1 = pk2(2.f * cb1, 2.f * cb1);
        // chains: 0:[m0,a,lo] 1:[m0,a,hi] 2:[m0,b,lo] 3:[m0,b,hi]
        //         4:[m1,a,lo] 5:[m1,a,hi] 6:[m1,b,lo] 7:[m1,b,hi]
        u64p c1[8], c2[8];
#pragma unroll
        for (int q = 0; q < 8; q++) { c1[q] = 0ull; c2[q] = 0ull; }
        const ulonglong2* CA = reinterpret_cast<const ulonglong2*>(g_CS + (size_t)p0 * KPAD);
        const ulonglong2* CB = reinterpret_cast<const ulonglong2*>(g_CS + (size_t)(p0 + 1) * KPAD);
        for (int it = L - 1; it >= 0; it--) {
            ulonglong2 fa  = __ldg(CA + idx0 + it);
            ulonglong2 fah = __ldg(CA + idx0 + L + it);
            ulonglong2 fb  = __ldg(CB + idx0 + it);
            ulonglong2 fbh = __ldg(CB + idx0 + L + it);
            clenshaw_step(c1[0], c2[0], t2a0, negv, fa.y);
            clenshaw_step(c1[1], c2[1], t2a0, negv, fah.y);
            clenshaw_step(c1[2], c2[2], t2b0, negv, fb.y);
            clenshaw_step(c1[3], c2[3], t2b0, negv, fbh.y);
            clenshaw_step(c1[4], c2[4], t2a1, negv, fa.y);
            clenshaw_step(c1[5], c2[5], t2a1, negv, fah.y);
            clenshaw_step(c1[6], c2[6], t2b1, negv, fb.y);
            clenshaw_step(c1[7], c2[7], t2b1, negv, fbh.y);
            clenshaw_step(c1[0], c2[0], t2a0, negv, fa.x);
            clenshaw_step(c1[1], c2[1], t2a0, negv, fah.x);
            clenshaw_step(c1[2], c2[2], t2b0, negv, fb.x);
            clenshaw_step(c1[3], c2[3], t2b0, negv, fbh.x);
            clenshaw_step(c1[4], c2[4], t2a1, negv, fa.x);
            clenshaw_step(c1[5], c2[5], t2a1, negv, fah.x);
            clenshaw_step(c1[6], c2[6], t2b1, negv, fb.x);
            clenshaw_step(c1[7], c2[7], t2b1, negv, fbh.x);
        }
        float tot0 = clenshaw_fin(c1[0], c2[0], fklo, ba0, ca0, sa0)
                   + clenshaw_fin(c1[1], c2[1], fkhi, ba0, ca0, sa0)
                   + clenshaw_fin(c1[2], c2[2], fklo, bb0, cb0, sb0)
                   + clenshaw_fin(c1[3], c2[3], fkhi, bb0, cb0, sb0);
        atomicAdd(out + m0, tot0);
        if (has1) {
            float tot1 = clenshaw_fin(c1[4], c2[4], fklo, ba1, ca1, sa1)
                       + clenshaw_fin(c1[5], c2[5], fkhi, ba1, ca1, sa1)
                       + clenshaw_fin(c1[6], c2[6], fklo, bb1, cb1, sb1)
                       + clenshaw_fin(c1[7], c2[7], fkhi, bb1, cb1, sb1);
            atomicAdd(out + m1, tot1);
        }
    } else if (p0 < P) {   // odd-P tail: single slice, two m
        float ba0 = g_B[(size_t)p0 * M + m0];
        float ba1 = has1 ? g_B[(size_t)p0 * M + m1] : 0.f;
        float sa0, ca0, sa1, ca1;
        __sincosf(TWO_PI_F * ba0, &sa0, &ca0);
        __sincosf(TWO_PI_F * ba1, &sa1, &ca1);
        u64p t2a0 = pk2(2.f * ca0, 2.f * ca0);
        u64p t2a1 = pk2(2.f * ca1, 2.f * ca1);
        u64p c1[4], c2[4];
#pragma unroll
        for (int q = 0; q < 4; q++) { c1[q] = 0ull; c2[q] = 0ull; }
        const ulonglong2* CA = reinterpret_cast<const ulonglong2*>(g_CS + (size_t)p0 * KPAD);
        for (int it = L - 1; it >= 0; it--) {
            ulonglong2 fa  = __ldg(CA + idx0 + it);
            ulonglong2 fah = __ldg(CA + idx0 + L + it);
            clenshaw_step(c1[0], c2[0], t2a0, negv, fa.y);
            clenshaw_step(c1[1], c2[1], t2a0, negv, fah.y);
            clenshaw_step(c1[2], c2[2], t2a1, negv, fa.y);
            clenshaw_step(c1[3], c2[3], t2a1, negv, fah.y);
            clenshaw_step(c1[0], c2[0], t2a0, negv, fa.x);
            clenshaw_step(c1[1], c2[1], t2a0, negv, fah.x);
            clenshaw_step(c1[2], c2[2], t2a1, negv, fa.x);
            clenshaw_step(c1[3], c2[3], t2a1, negv, fah.x);
        }
        float tot0 = clenshaw_fin(c1[0], c2[0], fklo, ba0, ca0, sa0)
                   + clenshaw_fin(c1[1], c2[1], fkhi, ba0, ca0, sa0);
        atomicAdd(out + m0, tot0);
        if (has1) {
            float tot1 = clenshaw_fin(c1[2], c2[2], fklo, ba1, ca1, sa1)
                       + clenshaw_fin(c1[3], c2[3], fkhi, ba1, ca1, sa1);
            atomicAdd(out + m1, tot1);
        }
    }
}

extern "C" void kernel_launch(void* const* d_in, const int* in_sizes, int n_in,
                              void* d_out, int out_size) {
    const float* x     = (const float*)d_in[0];
    const float* y     = (const float*)d_in[1];
    const float* w     = (const float*)d_in[2];
    const float* scale = (const float*)d_in[3];
    const float* xis   = (const float*)d_in[4];
    float* out = (float*)d_out;

    int N = in_sizes[2];
    int d = in_sizes[0] / N;
    int M = out_size;
    int P = in_sizes[4] / d;

    int nb = (N + M + 255) / 256;
    norm_kft_kernel<<<nb, 256>>>(x, y, scale, out, N, M, d, (float)d, P);
    int nmax = (N > M) ? N : M;
    dim3 pgrid((nmax + PROJ_PTS - 1) / PROJ_PTS, 2, 2);
    proj5_kernel<<<pgrid, 256>>>(x, y, xis, N, M, P);
    adjoint_kernel<<<dim3(P, AZ), ABLK>>>(w, N);
    int Mh = (M + 1) / 2;
    int ngroups = (P + PG - 1) / PG;
    forward_kernel<<<dim3((Mh + FBLK - 1) / FBLK, ngroups), FBLK>>>(out, M, P);
}